// round 1
// baseline (speedup 1.0000x reference)
#include <cuda_runtime.h>

#define BSZ  32
#define NUMS 512
#define FEAT 1024
#define NH   8
#define HLEN 128

// scratch (allocation-free rule: __device__ globals)
__device__ float g_Q [(size_t)BSZ * NH * NUMS * HLEN];   // Q*(gate^2*scale), [b,h,n,d]
__device__ float g_Vp[(size_t)BSZ * NUMS * FEAT];        // att@V, [b,n,f]
__device__ float g_gate2[BSZ * FEAT];                    // gate^2 * 1/sqrt(hlen)

// ---------------------------------------------------------------- gate^2
__global__ void gate_kernel(const float* __restrict__ x2) {
    int b = blockIdx.y;
    int f = blockIdx.x * 256 + threadIdx.x;
    const float* p = x2 + (size_t)b * NUMS * FEAT + f;
    float s = 0.f;
#pragma unroll 8
    for (int n = 0; n < NUMS; n++) s += p[(size_t)n * FEAT];
    float g = s * (1.0f / NUMS);
    g_gate2[b * FEAT + f] = g * g * 0.08838834764831845f;  // 1/sqrt(128)
}

// ---------------------------------------------------------------- Q projection GEMM
// C[m, col] = sum_f x1[m,f] * Wq[h, f, d]  (col = h*128+d), epilogue: (+bq)*gate2
__global__ __launch_bounds__(256) void qproj_kernel(
    const float* __restrict__ x1, const float* __restrict__ Wq,
    const float* __restrict__ bq)
{
    __shared__ float As[16][132];   // A transposed: As[k][m]
    __shared__ float Bs[16][132];
    const int m0 = blockIdx.y * 128;
    const int n0 = blockIdx.x * 128;
    const int tid = threadIdx.x;
    const int tx = tid & 15, ty = tid >> 4;

    float acc[8][8];
#pragma unroll
    for (int i = 0; i < 8; i++)
#pragma unroll
        for (int j = 0; j < 8; j++) acc[i][j] = 0.f;

    const int ar = tid >> 1;            // 0..127
    const int ac = (tid & 1) * 8;       // 0 or 8
    const int bkr = tid >> 4;           // 0..15
    const int bc = (tid & 15) * 8;      // 0..120
    const int hB = (n0 + bc) >> 7;
    const int dB = (n0 + bc) & 127;
    const float* Bp = Wq + (size_t)hB * FEAT * HLEN + dB;

    for (int k0 = 0; k0 < FEAT; k0 += 16) {
        const float4* ap = (const float4*)(x1 + (size_t)(m0 + ar) * FEAT + k0 + ac);
        float4 a0 = ap[0], a1 = ap[1];
        As[ac + 0][ar] = a0.x; As[ac + 1][ar] = a0.y;
        As[ac + 2][ar] = a0.z; As[ac + 3][ar] = a0.w;
        As[ac + 4][ar] = a1.x; As[ac + 5][ar] = a1.y;
        As[ac + 6][ar] = a1.z; As[ac + 7][ar] = a1.w;
        const float4* bp = (const float4*)(Bp + (size_t)(k0 + bkr) * HLEN);
        *(float4*)&Bs[bkr][bc]     = bp[0];
        *(float4*)&Bs[bkr][bc + 4] = bp[1];
        __syncthreads();
#pragma unroll
        for (int k = 0; k < 16; k++) {
            float a[8], b[8];
#pragma unroll
            for (int i = 0; i < 8; i++) a[i] = As[k][ty * 8 + i];
#pragma unroll
            for (int j = 0; j < 8; j++) b[j] = Bs[k][tx * 8 + j];
#pragma unroll
            for (int i = 0; i < 8; i++)
#pragma unroll
                for (int j = 0; j < 8; j++) acc[i][j] += a[i] * b[j];
        }
        __syncthreads();
    }
#pragma unroll
    for (int i = 0; i < 8; i++) {
        int m = m0 + ty * 8 + i;
        int bidx = m >> 9, n = m & 511;
#pragma unroll
        for (int j = 0; j < 8; j++) {
            int col = n0 + tx * 8 + j;
            float v = (acc[i][j] + bq[col]) * g_gate2[bidx * FEAT + col];
            int hh = col >> 7, d = col & 127;
            g_Q[(((size_t)bidx * NH + hh) * NUMS + n) * HLEN + d] = v;
        }
    }
}

// ---------------------------------------------------------------- fused attention
// per (b, h, 64-row tile): S = Qs K^T (scale/gate pre-folded), mask, softmax,
// write att, then att @ V.
__global__ __launch_bounds__(256) void attn_kernel(
    const float* __restrict__ x1, const unsigned* __restrict__ mask,
    float* __restrict__ att_out)
{
    extern __shared__ float sm[];
    float* Qt = sm;                  // [128][65] transposed Q tile
    float* KV = sm + 8320;           // 8448 floats: K^T tile [128][65] / V tile [64][132]
    float* S  = sm + 8320 + 8448;    // [64][516]
    const int tid = threadIdx.x;
    const int tx = tid & 15, ty = tid >> 4;
    const int n0 = blockIdx.x * 64;
    const int h = blockIdx.y, b = blockIdx.z;

    const float* Qg = g_Q + (((size_t)b * NH + h) * NUMS + n0) * HLEN;
    for (int idx = tid; idx < 64 * 128; idx += 256) {
        int r = idx >> 7, k = idx & 127;
        Qt[k * 65 + r] = Qg[idx];
    }

    const float* Kg = x1 + (size_t)b * NUMS * FEAT + (size_t)h * HLEN;
    for (int mt = 0; mt < 8; mt++) {
        __syncthreads();
        for (int idx = tid; idx < 64 * 128; idx += 256) {
            int r = idx >> 7, k = idx & 127;
            KV[k * 65 + r] = Kg[(size_t)(mt * 64 + r) * FEAT + k];
        }
        __syncthreads();
        float acc[4][4];
#pragma unroll
        for (int i = 0; i < 4; i++)
#pragma unroll
            for (int j = 0; j < 4; j++) acc[i][j] = 0.f;
#pragma unroll 8
        for (int k = 0; k < 128; k++) {
            float a[4], bb[4];
#pragma unroll
            for (int i = 0; i < 4; i++) a[i]  = Qt[k * 65 + ty * 4 + i];
#pragma unroll
            for (int j = 0; j < 4; j++) bb[j] = KV[k * 65 + tx * 4 + j];
#pragma unroll
            for (int i = 0; i < 4; i++)
#pragma unroll
                for (int j = 0; j < 4; j++) acc[i][j] += a[i] * bb[j];
        }
#pragma unroll
        for (int i = 0; i < 4; i++)
#pragma unroll
            for (int j = 0; j < 4; j++)
                S[(ty * 4 + i) * 516 + mt * 64 + tx * 4 + j] = acc[i][j];
    }
    __syncthreads();

    // masked softmax, warp per row; write att to global, keep probs in S
    const int wid = tid >> 5, lane = tid & 31;
    for (int r = wid; r < 64; r += 8) {
        float* Sr = S + r * 516;
        const unsigned* mrow = mask + (size_t)b * NUMS * NUMS + (size_t)(n0 + r) * NUMS;
        float mx = -1e30f;
        for (int c = lane; c < NUMS; c += 32) {
            float v = mrow[c] ? -1e9f : Sr[c];
            Sr[c] = v;
            mx = fmaxf(mx, v);
        }
#pragma unroll
        for (int o = 16; o; o >>= 1) mx = fmaxf(mx, __shfl_xor_sync(0xffffffffu, mx, o));
        float sum = 0.f;
        for (int c = lane; c < NUMS; c += 32) {
            float e = __expf(Sr[c] - mx);
            Sr[c] = e;
            sum += e;
        }
#pragma unroll
        for (int o = 16; o; o >>= 1) sum += __shfl_xor_sync(0xffffffffu, sum, o);
        float inv = 1.0f / sum;
        float* arow = att_out + (((size_t)b * NH + h) * NUMS + (n0 + r)) * NUMS;
        for (int c = lane; c < NUMS; c += 32) {
            float p = Sr[c] * inv;
            Sr[c] = p;
            arow[c] = p;
        }
    }
    __syncthreads();

    // att @ V : C[64][128], thread computes 4x8
    float acc2[4][8];
#pragma unroll
    for (int i = 0; i < 4; i++)
#pragma unroll
        for (int j = 0; j < 8; j++) acc2[i][j] = 0.f;

    for (int kt = 0; kt < 8; kt++) {
        __syncthreads();
        for (int idx = tid; idx < 64 * 128; idx += 256) {
            int kk = idx >> 7, c = idx & 127;
            KV[kk * 132 + c] = Kg[(size_t)(kt * 64 + kk) * FEAT + c];
        }
        __syncthreads();
#pragma unroll 4
        for (int kk = 0; kk < 64; kk++) {
            float a[4];
#pragma unroll
            for (int i = 0; i < 4; i++) a[i] = S[(ty * 4 + i) * 516 + kt * 64 + kk];
            float4 b0 = *(const float4*)&KV[kk * 132 + tx * 8];
            float4 b1 = *(const float4*)&KV[kk * 132 + tx * 8 + 4];
            float bb[8] = {b0.x, b0.y, b0.z, b0.w, b1.x, b1.y, b1.z, b1.w};
#pragma unroll
            for (int i = 0; i < 4; i++)
#pragma unroll
                for (int j = 0; j < 8; j++) acc2[i][j] += a[i] * bb[j];
        }
    }
    float* Vo = g_Vp + (size_t)b * NUMS * FEAT + (size_t)n0 * FEAT + (size_t)h * HLEN;
#pragma unroll
    for (int i = 0; i < 4; i++) {
        float4 w0 = {acc2[i][0], acc2[i][1], acc2[i][2], acc2[i][3]};
        float4 w1 = {acc2[i][4], acc2[i][5], acc2[i][6], acc2[i][7]};
        *(float4*)&Vo[(size_t)(ty * 4 + i) * FEAT + tx * 8]     = w0;
        *(float4*)&Vo[(size_t)(ty * 4 + i) * FEAT + tx * 8 + 4] = w1;
    }
}

// ---------------------------------------------------------------- output GEMM
// out = relu(g_Vp @ Wl + bl) + x1
__global__ __launch_bounds__(256) void out_kernel(
    const float* __restrict__ Wl, const float* __restrict__ bl,
    const float* __restrict__ x1, float* __restrict__ out)
{
    __shared__ float As[16][132];
    __shared__ float Bs[16][132];
    const int m0 = blockIdx.y * 128;
    const int n0 = blockIdx.x * 128;
    const int tid = threadIdx.x;
    const int tx = tid & 15, ty = tid >> 4;

    float acc[8][8];
#pragma unroll
    for (int i = 0; i < 8; i++)
#pragma unroll
        for (int j = 0; j < 8; j++) acc[i][j] = 0.f;

    const int ar = tid >> 1;
    const int ac = (tid & 1) * 8;
    const int bkr = tid >> 4;
    const int bc = (tid & 15) * 8;

    for (int k0 = 0; k0 < FEAT; k0 += 16) {
        const float4* ap = (const float4*)(g_Vp + (size_t)(m0 + ar) * FEAT + k0 + ac);
        float4 a0 = ap[0], a1 = ap[1];
        As[ac + 0][ar] = a0.x; As[ac + 1][ar] = a0.y;
        As[ac + 2][ar] = a0.z; As[ac + 3][ar] = a0.w;
        As[ac + 4][ar] = a1.x; As[ac + 5][ar] = a1.y;
        As[ac + 6][ar] = a1.z; As[ac + 7][ar] = a1.w;
        const float4* bp = (const float4*)(Wl + (size_t)(k0 + bkr) * FEAT + n0 + bc);
        *(float4*)&Bs[bkr][bc]     = bp[0];
        *(float4*)&Bs[bkr][bc + 4] = bp[1];
        __syncthreads();
#pragma unroll
        for (int k = 0; k < 16; k++) {
            float a[8], b[8];
#pragma unroll
            for (int i = 0; i < 8; i++) a[i] = As[k][ty * 8 + i];
#pragma unroll
            for (int j = 0; j < 8; j++) b[j] = Bs[k][tx * 8 + j];
#pragma unroll
            for (int i = 0; i < 8; i++)
#pragma unroll
                for (int j = 0; j < 8; j++) acc[i][j] += a[i] * b[j];
        }
        __syncthreads();
    }
#pragma unroll
    for (int i = 0; i < 8; i++) {
        int m = m0 + ty * 8 + i;
#pragma unroll
        for (int j = 0; j < 8; j++) {
            int col = n0 + tx * 8 + j;
            float v = acc[i][j] + bl[col];
            v = fmaxf(v, 0.f) + x1[(size_t)m * FEAT + col];
            out[(size_t)m * FEAT + col] = v;
        }
    }
}

// ----------------------------------------------------------------
extern "C" void kernel_launch(void* const* d_in, const int* in_sizes, int n_in,
                              void* d_out, int out_size) {
    const float*    x1   = (const float*)d_in[0];
    const float*    x2   = (const float*)d_in[1];
    // d_in[2] = adj, d_in[3] = bias : unused by the reference forward
    const unsigned* mask = (const unsigned*)d_in[4];
    const float*    Wq   = (const float*)d_in[5];
    const float*    bq   = (const float*)d_in[6];
    const float*    Wl   = (const float*)d_in[7];
    const float*    bl   = (const float*)d_in[8];
    float* out = (float*)d_out;
    float* att = out + (size_t)BSZ * NUMS * FEAT;   // tuple: (xout, att)

    dim3 gg(FEAT / 256, BSZ);
    gate_kernel<<<gg, 256>>>(x2);

    dim3 ggemm(FEAT / 128, (BSZ * NUMS) / 128);
    qproj_kernel<<<ggemm, 256>>>(x1, Wq, bq);

    const int ATTN_SMEM = (8320 + 8448 + 64 * 516) * 4;  // 199168 B
    cudaFuncSetAttribute(attn_kernel,
                         cudaFuncAttributeMaxDynamicSharedMemorySize, ATTN_SMEM);
    dim3 ga(NUMS / 64, NH, BSZ);
    attn_kernel<<<ga, 256, ATTN_SMEM>>>(x1, mask, att);

    out_kernel<<<ggemm, 256>>>(Wl, bl, x1, out);
}

// round 5
// speedup vs baseline: 1.2554x; 1.2554x over previous
#include <cuda_runtime.h>
#include <cuda_bf16.h>
#include <cstdint>

#define BSZ  32
#define NUMS 512
#define FEAT 1024
#define NH   8
#define HLEN 128

// scratch (allocation-free rule: __device__ globals)
__device__ float g_Q [(size_t)BSZ * NH * NUMS * HLEN];   // Q*(gate^2*scale), [b,h,n,d]
__device__ float g_Vp[(size_t)BSZ * NUMS * FEAT];        // att@V, [b,n,f]
__device__ float g_gate2[BSZ * FEAT];                    // gate^2 * 1/sqrt(hlen)

// ---------------------------------------------------------------- helpers
__device__ __forceinline__ uint32_t pack2(float a, float b) {
    __nv_bfloat162 t = __floats2bfloat162_rn(a, b);
    return *(uint32_t*)&t;
}
__device__ __forceinline__ float hif(float f) {          // bf16-rounded value
    return __bfloat162float(__float2bfloat16_rn(f));
}
__device__ __forceinline__ void mma16816(float* c, const uint32_t* a, const uint32_t* b) {
    asm volatile(
        "mma.sync.aligned.m16n8k16.row.col.f32.bf16.bf16.f32 "
        "{%0,%1,%2,%3}, {%4,%5,%6,%7}, {%8,%9}, {%0,%1,%2,%3};"
        : "+f"(c[0]), "+f"(c[1]), "+f"(c[2]), "+f"(c[3])
        : "r"(a[0]), "r"(a[1]), "r"(a[2]), "r"(a[3]), "r"(b[0]), "r"(b[1]));
}

#define SSTR  40                      // smem row stride (bf16 elems) = 80B
#define PIECE (128 * SSTR)            // one 128x32 tile piece
// smem: [buf][Ah, Al, Bh, Bl] each PIECE; total 8*PIECE*2B = 81920 B

// ================================================================
// C[16384, 1024] = A[.,1024] @ B   (bf16 hi/lo split, 3 mma products)
// MODE 0: A = arg, B = Wq[h][k][d] head-blocked, epi (acc+bq)*gate2 -> g_Q
// MODE 1: A = g_Vp (device symbol, selected IN KERNEL), B = Wl[k][n],
//         epi relu(acc+bl)+x1 -> out
template <int MODE>
__global__ void __launch_bounds__(256, 1) gemm_mma(
    const float* __restrict__ Ain, const float* __restrict__ Bw,
    const float* __restrict__ bias, const float* __restrict__ res,
    float* __restrict__ Cout)
{
    extern __shared__ __nv_bfloat16 smb[];
    const float* __restrict__ A = (MODE == 1) ? (const float*)g_Vp : Ain;
    const int tid = threadIdx.x;
    const int n0 = blockIdx.x * 128;
    const int m0 = blockIdx.y * 128;
    const int wid = tid >> 5, lane = tid & 31;
    const int wm = (wid >> 2) * 64;        // warp m-offset (0/64)
    const int wn = (wid & 3) * 32;         // warp n-offset (0..96)
    const int g = lane >> 2, q = lane & 3; // fragment group / quad

    const size_t ldb = (MODE == 0) ? HLEN : FEAT;
    const float* Bp = (MODE == 0)
        ? Bw + (size_t)(n0 >> 7) * FEAT * HLEN
        : Bw + n0;

    // staged-load addressing
    const int arow = tid >> 1, akh = (tid & 1) * 16;           // A: row, k-half
    const int bn4 = (tid & 31) * 4, bkg = (tid >> 5) * 4;      // B: n base, k base
    const float* aPtr = A + (size_t)(m0 + arow) * FEAT + akh;
    const float* bPtr = Bp + (size_t)bkg * ldb + bn4;

    float aS[16], bS[16];
    float c[4][4][4];
#pragma unroll
    for (int i = 0; i < 4; i++)
#pragma unroll
        for (int j = 0; j < 4; j++)
#pragma unroll
            for (int k = 0; k < 4; k++) c[i][j][k] = 0.f;

    // ---- stage chunk k0 into registers
    auto loadStage = [&](int k0) {
#pragma unroll
        for (int i = 0; i < 4; i++)
            *(float4*)&aS[i * 4] = *(const float4*)(aPtr + k0 + i * 4);
        const float* bp = bPtr + (size_t)k0 * ldb;
#pragma unroll
        for (int i = 0; i < 4; i++)
            *(float4*)&bS[i * 4] = *(const float4*)(bp + i * ldb);
    };
    // ---- convert + store staged regs into smem buffer
    auto storeStage = [&](int buf) {
        __nv_bfloat16* Ah = smb + buf * 4 * PIECE;
        __nv_bfloat16* Al = Ah + PIECE;
        __nv_bfloat16* Bh = Al + PIECE;
        __nv_bfloat16* Bl = Bh + PIECE;
#pragma unroll
        for (int i = 0; i < 4; i++) {
            float f0 = aS[i*4+0], f1 = aS[i*4+1], f2 = aS[i*4+2], f3 = aS[i*4+3];
            float h0 = hif(f0), h1 = hif(f1), h2 = hif(f2), h3 = hif(f3);
            int off = arow * SSTR + akh + i * 4;
            *(uint2*)&Ah[off] = make_uint2(pack2(f0, f1), pack2(f2, f3));
            *(uint2*)&Al[off] = make_uint2(pack2(f0-h0, f1-h1), pack2(f2-h2, f3-h3));
        }
#pragma unroll
        for (int j = 0; j < 4; j++) {
            // bS[i*4+j] = element (k = bkg+i, n = bn4+j)
            float f0 = bS[0*4+j], f1 = bS[1*4+j], f2 = bS[2*4+j], f3 = bS[3*4+j];
            float h0 = hif(f0), h1 = hif(f1), h2 = hif(f2), h3 = hif(f3);
            int off = (bn4 + j) * SSTR + bkg;
            *(uint32_t*)&Bh[off]     = pack2(f0, f1);
            *(uint32_t*)&Bh[off + 2] = pack2(f2, f3);
            *(uint32_t*)&Bl[off]     = pack2(f0-h0, f1-h1);
            *(uint32_t*)&Bl[off + 2] = pack2(f2-h2, f3-h3);
        }
    };
    // ---- mma compute on buffer
    auto compute = [&](int buf) {
        const __nv_bfloat16* Ah = smb + buf * 4 * PIECE;
        const __nv_bfloat16* Al = Ah + PIECE;
        const __nv_bfloat16* Bh = Al + PIECE;
        const __nv_bfloat16* Bl = Bh + PIECE;
#pragma unroll
        for (int ks = 0; ks < 2; ks++) {
            const int kb = ks * 16 + q * 2;
            uint32_t ah[4][4], al[4][4], bh[4][2], bl[4][2];
#pragma unroll
            for (int mt = 0; mt < 4; mt++) {
                int r0 = (wm + mt * 16 + g) * SSTR + kb;
                int r1 = r0 + 8 * SSTR;
                ah[mt][0] = *(const uint32_t*)&Ah[r0];
                ah[mt][1] = *(const uint32_t*)&Ah[r1];
                ah[mt][2] = *(const uint32_t*)&Ah[r0 + 8];
                ah[mt][3] = *(const uint32_t*)&Ah[r1 + 8];
                al[mt][0] = *(const uint32_t*)&Al[r0];
                al[mt][1] = *(const uint32_t*)&Al[r1];
                al[mt][2] = *(const uint32_t*)&Al[r0 + 8];
                al[mt][3] = *(const uint32_t*)&Al[r1 + 8];
            }
#pragma unroll
            for (int nt = 0; nt < 4; nt++) {
                int rb = (wn + nt * 8 + g) * SSTR + kb;
                bh[nt][0] = *(const uint32_t*)&Bh[rb];
                bh[nt][1] = *(const uint32_t*)&Bh[rb + 8];
                bl[nt][0] = *(const uint32_t*)&Bl[rb];
                bl[nt][1] = *(const uint32_t*)&Bl[rb + 8];
            }
#pragma unroll
            for (int mt = 0; mt < 4; mt++)
#pragma unroll
                for (int nt = 0; nt < 4; nt++) {
                    mma16816(c[mt][nt], ah[mt], bh[nt]);
                    mma16816(c[mt][nt], ah[mt], bl[nt]);
                    mma16816(c[mt][nt], al[mt], bh[nt]);
                }
        }
    };

    loadStage(0);
    storeStage(0);
    __syncthreads();
    for (int ch = 0; ch < 32; ch++) {
        const int buf = ch & 1;
        if (ch < 31) loadStage((ch + 1) * 32);
        compute(buf);
        if (ch < 31) storeStage(buf ^ 1);
        __syncthreads();
    }

    // ---- epilogue
#pragma unroll
    for (int mt = 0; mt < 4; mt++)
#pragma unroll
        for (int nt = 0; nt < 4; nt++) {
            const int dcol = wn + nt * 8 + q * 2;
            const int col = n0 + dcol;
#pragma unroll
            for (int hh = 0; hh < 2; hh++) {
                const int m = m0 + wm + mt * 16 + g + hh * 8;
                float v0 = c[mt][nt][hh * 2 + 0];
                float v1 = c[mt][nt][hh * 2 + 1];
                if (MODE == 0) {
                    const int bi = m >> 9, ns = m & 511, h = n0 >> 7;
                    float2 o;
                    o.x = (v0 + bias[col])     * g_gate2[bi * FEAT + col];
                    o.y = (v1 + bias[col + 1]) * g_gate2[bi * FEAT + col + 1];
                    *(float2*)&g_Q[(((size_t)bi * NH + h) * NUMS + ns) * HLEN + dcol] = o;
                } else {
                    float2 o;
                    o.x = fmaxf(v0 + bias[col], 0.f)     + res[(size_t)m * FEAT + col];
                    o.y = fmaxf(v1 + bias[col + 1], 0.f) + res[(size_t)m * FEAT + col + 1];
                    *(float2*)&Cout[(size_t)m * FEAT + col] = o;
                }
            }
        }
}

// ---------------------------------------------------------------- gate^2
__global__ void gate_kernel(const float* __restrict__ x2) {
    int b = blockIdx.y;
    int f = blockIdx.x * 256 + threadIdx.x;
    const float* p = x2 + (size_t)b * NUMS * FEAT + f;
    float s = 0.f;
#pragma unroll 8
    for (int n = 0; n < NUMS; n++) s += p[(size_t)n * FEAT];
    float g = s * (1.0f / NUMS);
    g_gate2[b * FEAT + f] = g * g * 0.08838834764831845f;  // 1/sqrt(128)
}

// ---------------------------------------------------------------- fused attention
__global__ __launch_bounds__(256) void attn_kernel(
    const float* __restrict__ x1, const unsigned* __restrict__ mask,
    float* __restrict__ att_out)
{
    extern __shared__ float smf[];
    float* Qt = smf;                  // [128][65] transposed Q tile
    float* KV = smf + 8320;           // K^T tile [128][65] / V tile [64][132]
    float* S  = smf + 8320 + 8448;    // [64][516]
    const int tid = threadIdx.x;
    const int tx = tid & 15, ty = tid >> 4;
    const int n0 = blockIdx.x * 64;
    const int h = blockIdx.y, b = blockIdx.z;

    const float* Qg = g_Q + (((size_t)b * NH + h) * NUMS + n0) * HLEN;
    for (int idx = tid; idx < 64 * 128; idx += 256) {
        int r = idx >> 7, k = idx & 127;
        Qt[k * 65 + r] = Qg[idx];
    }

    const float* Kg = x1 + (size_t)b * NUMS * FEAT + (size_t)h * HLEN;
    for (int mt = 0; mt < 8; mt++) {
        __syncthreads();
        for (int idx = tid; idx < 64 * 128; idx += 256) {
            int r = idx >> 7, k = idx & 127;
            KV[k * 65 + r] = Kg[(size_t)(mt * 64 + r) * FEAT + k];
        }
        __syncthreads();
        float acc[4][4];
#pragma unroll
        for (int i = 0; i < 4; i++)
#pragma unroll
            for (int j = 0; j < 4; j++) acc[i][j] = 0.f;
#pragma unroll 8
        for (int k = 0; k < 128; k++) {
            float a[4], bb[4];
#pragma unroll
            for (int i = 0; i < 4; i++) a[i]  = Qt[k * 65 + ty * 4 + i];
#pragma unroll
            for (int j = 0; j < 4; j++) bb[j] = KV[k * 65 + tx * 4 + j];
#pragma unroll
            for (int i = 0; i < 4; i++)
#pragma unroll
                for (int j = 0; j < 4; j++) acc[i][j] += a[i] * bb[j];
        }
#pragma unroll
        for (int i = 0; i < 4; i++)
#pragma unroll
            for (int j = 0; j < 4; j++)
                S[(ty * 4 + i) * 516 + mt * 64 + tx * 4 + j] = acc[i][j];
    }
    __syncthreads();

    const int wid = tid >> 5, lane = tid & 31;
    for (int r = wid; r < 64; r += 8) {
        float* Sr = S + r * 516;
        const unsigned* mrow = mask + (size_t)b * NUMS * NUMS + (size_t)(n0 + r) * NUMS;
        float mx = -1e30f;
        for (int c = lane; c < NUMS; c += 32) {
            float v = mrow[c] ? -1e9f : Sr[c];
            Sr[c] = v;
            mx = fmaxf(mx, v);
        }
#pragma unroll
        for (int o = 16; o; o >>= 1) mx = fmaxf(mx, __shfl_xor_sync(0xffffffffu, mx, o));
        float sum = 0.f;
        for (int c = lane; c < NUMS; c += 32) {
            float e = __expf(Sr[c] - mx);
            Sr[c] = e;
            sum += e;
        }
#pragma unroll
        for (int o = 16; o; o >>= 1) sum += __shfl_xor_sync(0xffffffffu, sum, o);
        float inv = 1.0f / sum;
        float* arow = att_out + (((size_t)b * NH + h) * NUMS + (n0 + r)) * NUMS;
        for (int c = lane; c < NUMS; c += 32) {
            float p = Sr[c] * inv;
            Sr[c] = p;
            arow[c] = p;
        }
    }
    __syncthreads();

    float acc2[4][8];
#pragma unroll
    for (int i = 0; i < 4; i++)
#pragma unroll
        for (int j = 0; j < 8; j++) acc2[i][j] = 0.f;

    for (int kt = 0; kt < 8; kt++) {
        __syncthreads();
        for (int idx = tid; idx < 64 * 128; idx += 256) {
            int kk = idx >> 7, c = idx & 127;
            KV[kk * 132 + c] = Kg[(size_t)(kt * 64 + kk) * FEAT + c];
        }
        __syncthreads();
#pragma unroll 4
        for (int kk = 0; kk < 64; kk++) {
            float a[4];
#pragma unroll
            for (int i = 0; i < 4; i++) a[i] = S[(ty * 4 + i) * 516 + kt * 64 + kk];
            float4 b0 = *(const float4*)&KV[kk * 132 + tx * 8];
            float4 b1 = *(const float4*)&KV[kk * 132 + tx * 8 + 4];
            float bb[8] = {b0.x, b0.y, b0.z, b0.w, b1.x, b1.y, b1.z, b1.w};
#pragma unroll
            for (int i = 0; i < 4; i++)
#pragma unroll
                for (int j = 0; j < 8; j++) acc2[i][j] += a[i] * bb[j];
        }
    }
    float* Vo = g_Vp + (size_t)b * NUMS * FEAT + (size_t)n0 * FEAT + (size_t)h * HLEN;
#pragma unroll
    for (int i = 0; i < 4; i++) {
        float4 w0 = {acc2[i][0], acc2[i][1], acc2[i][2], acc2[i][3]};
        float4 w1 = {acc2[i][4], acc2[i][5], acc2[i][6], acc2[i][7]};
        *(float4*)&Vo[(size_t)(ty * 4 + i) * FEAT + tx * 8]     = w0;
        *(float4*)&Vo[(size_t)(ty * 4 + i) * FEAT + tx * 8 + 4] = w1;
    }
}

// ----------------------------------------------------------------
extern "C" void kernel_launch(void* const* d_in, const int* in_sizes, int n_in,
                              void* d_out, int out_size) {
    const float*    x1   = (const float*)d_in[0];
    const float*    x2   = (const float*)d_in[1];
    const unsigned* mask = (const unsigned*)d_in[4];
    const float*    Wq   = (const float*)d_in[5];
    const float*    bq   = (const float*)d_in[6];
    const float*    Wl   = (const float*)d_in[7];
    const float*    bl   = (const float*)d_in[8];
    float* out = (float*)d_out;
    float* att = out + (size_t)BSZ * NUMS * FEAT;   // tuple: (xout, att)

    dim3 gg(FEAT / 256, BSZ);
    gate_kernel<<<gg, 256>>>(x2);

    const int GEMM_SMEM = 8 * PIECE * 2;  // 81920 B
    cudaFuncSetAttribute(gemm_mma<0>, cudaFuncAttributeMaxDynamicSharedMemorySize, GEMM_SMEM);
    cudaFuncSetAttribute(gemm_mma<1>, cudaFuncAttributeMaxDynamicSharedMemorySize, GEMM_SMEM);

    dim3 ggemm(FEAT / 128, (BSZ * NUMS) / 128);
    gemm_mma<0><<<ggemm, 256, GEMM_SMEM>>>(x1, Wq, bq, nullptr, nullptr);

    const int ATTN_SMEM = (8320 + 8448 + 64 * 516) * 4;  // 199168 B
    cudaFuncSetAttribute(attn_kernel,
                         cudaFuncAttributeMaxDynamicSharedMemorySize, ATTN_SMEM);
    dim3 ga(NUMS / 64, NH, BSZ);
    attn_kernel<<<ga, 256, ATTN_SMEM>>>(x1, mask, att);

    // A = g_Vp selected inside the kernel (device symbol must NOT be a host-side arg)
    gemm_mma<1><<<ggemm, 256, GEMM_SMEM>>>(nullptr, Wl, bl, x1, out);
}

// round 6
// speedup vs baseline: 1.9509x; 1.5541x over previous
#include <cuda_runtime.h>
#include <cuda_bf16.h>
#include <cstdint>

#define BSZ  32
#define NUMS 512
#define FEAT 1024
#define NH   8
#define HLEN 128

// scratch (allocation-free rule: __device__ globals)
__device__ float g_Q [(size_t)BSZ * NH * NUMS * HLEN];   // Q*(gate^2*scale), [b,h,n,d]
__device__ float g_Vp[(size_t)BSZ * NUMS * FEAT];        // att@V, [b,n,f]
__device__ float g_gate2[BSZ * FEAT];                    // gate^2 * 1/sqrt(hlen)

// ---------------------------------------------------------------- helpers
__device__ __forceinline__ uint32_t pack2(float a, float b) {
    __nv_bfloat162 t = __floats2bfloat162_rn(a, b);
    return *(uint32_t*)&t;
}
__device__ __forceinline__ float hif(float f) {          // bf16-rounded value
    return __bfloat162float(__float2bfloat16_rn(f));
}
__device__ __forceinline__ void cvt4(float4 v, uint2& hi, uint2& lo) {
    float hx = hif(v.x), hy = hif(v.y), hz = hif(v.z), hw = hif(v.w);
    hi = make_uint2(pack2(v.x, v.y), pack2(v.z, v.w));
    lo = make_uint2(pack2(v.x - hx, v.y - hy), pack2(v.z - hz, v.w - hw));
}
__device__ __forceinline__ void mma16816(float* c, const uint32_t* a, const uint32_t* b) {
    asm volatile(
        "mma.sync.aligned.m16n8k16.row.col.f32.bf16.bf16.f32 "
        "{%0,%1,%2,%3}, {%4,%5,%6,%7}, {%8,%9}, {%0,%1,%2,%3};"
        : "+f"(c[0]), "+f"(c[1]), "+f"(c[2]), "+f"(c[3])
        : "r"(a[0]), "r"(a[1]), "r"(a[2]), "r"(a[3]), "r"(b[0]), "r"(b[1]));
}

#define SSTR  40                      // gemm smem row stride (bf16 elems)
#define PIECE (128 * SSTR)

// ================================================================
// dense GEMMs (unchanged from R5-passing kernel)
template <int MODE>
__global__ void __launch_bounds__(256, 1) gemm_mma(
    const float* __restrict__ Ain, const float* __restrict__ Bw,
    const float* __restrict__ bias, const float* __restrict__ res,
    float* __restrict__ Cout)
{
    extern __shared__ __nv_bfloat16 smb[];
    const float* __restrict__ A = (MODE == 1) ? (const float*)g_Vp : Ain;
    const int tid = threadIdx.x;
    const int n0 = blockIdx.x * 128;
    const int m0 = blockIdx.y * 128;
    const int wid = tid >> 5, lane = tid & 31;
    const int wm = (wid >> 2) * 64;
    const int wn = (wid & 3) * 32;
    const int g = lane >> 2, q = lane & 3;

    const size_t ldb = (MODE == 0) ? HLEN : FEAT;
    const float* Bp = (MODE == 0)
        ? Bw + (size_t)(n0 >> 7) * FEAT * HLEN
        : Bw + n0;

    const int arow = tid >> 1, akh = (tid & 1) * 16;
    const int bn4 = (tid & 31) * 4, bkg = (tid >> 5) * 4;
    const float* aPtr = A + (size_t)(m0 + arow) * FEAT + akh;
    const float* bPtr = Bp + (size_t)bkg * ldb + bn4;

    float aS[16], bS[16];
    float c[4][4][4];
#pragma unroll
    for (int i = 0; i < 4; i++)
#pragma unroll
        for (int j = 0; j < 4; j++)
#pragma unroll
            for (int k = 0; k < 4; k++) c[i][j][k] = 0.f;

    auto loadStage = [&](int k0) {
#pragma unroll
        for (int i = 0; i < 4; i++)
            *(float4*)&aS[i * 4] = *(const float4*)(aPtr + k0 + i * 4);
        const float* bp = bPtr + (size_t)k0 * ldb;
#pragma unroll
        for (int i = 0; i < 4; i++)
            *(float4*)&bS[i * 4] = *(const float4*)(bp + i * ldb);
    };
    auto storeStage = [&](int buf) {
        __nv_bfloat16* Ah = smb + buf * 4 * PIECE;
        __nv_bfloat16* Al = Ah + PIECE;
        __nv_bfloat16* Bh = Al + PIECE;
        __nv_bfloat16* Bl = Bh + PIECE;
#pragma unroll
        for (int i = 0; i < 4; i++) {
            uint2 hi, lo;
            cvt4(*(float4*)&aS[i * 4], hi, lo);
            int off = arow * SSTR + akh + i * 4;
            *(uint2*)&Ah[off] = hi;
            *(uint2*)&Al[off] = lo;
        }
#pragma unroll
        for (int j = 0; j < 4; j++) {
            float f0 = bS[0*4+j], f1 = bS[1*4+j], f2 = bS[2*4+j], f3 = bS[3*4+j];
            float h0 = hif(f0), h1 = hif(f1), h2 = hif(f2), h3 = hif(f3);
            int off = (bn4 + j) * SSTR + bkg;
            *(uint32_t*)&Bh[off]     = pack2(f0, f1);
            *(uint32_t*)&Bh[off + 2] = pack2(f2, f3);
            *(uint32_t*)&Bl[off]     = pack2(f0-h0, f1-h1);
            *(uint32_t*)&Bl[off + 2] = pack2(f2-h2, f3-h3);
        }
    };
    auto compute = [&](int buf) {
        const __nv_bfloat16* Ah = smb + buf * 4 * PIECE;
        const __nv_bfloat16* Al = Ah + PIECE;
        const __nv_bfloat16* Bh = Al + PIECE;
        const __nv_bfloat16* Bl = Bh + PIECE;
#pragma unroll
        for (int ks = 0; ks < 2; ks++) {
            const int kb = ks * 16 + q * 2;
            uint32_t ah[4][4], al[4][4], bh[4][2], bl[4][2];
#pragma unroll
            for (int mt = 0; mt < 4; mt++) {
                int r0 = (wm + mt * 16 + g) * SSTR + kb;
                int r1 = r0 + 8 * SSTR;
                ah[mt][0] = *(const uint32_t*)&Ah[r0];
                ah[mt][1] = *(const uint32_t*)&Ah[r1];
                ah[mt][2] = *(const uint32_t*)&Ah[r0 + 8];
                ah[mt][3] = *(const uint32_t*)&Ah[r1 + 8];
                al[mt][0] = *(const uint32_t*)&Al[r0];
                al[mt][1] = *(const uint32_t*)&Al[r1];
                al[mt][2] = *(const uint32_t*)&Al[r0 + 8];
                al[mt][3] = *(const uint32_t*)&Al[r1 + 8];
            }
#pragma unroll
            for (int nt = 0; nt < 4; nt++) {
                int rb = (wn + nt * 8 + g) * SSTR + kb;
                bh[nt][0] = *(const uint32_t*)&Bh[rb];
                bh[nt][1] = *(const uint32_t*)&Bh[rb + 8];
                bl[nt][0] = *(const uint32_t*)&Bl[rb];
                bl[nt][1] = *(const uint32_t*)&Bl[rb + 8];
            }
#pragma unroll
            for (int mt = 0; mt < 4; mt++)
#pragma unroll
                for (int nt = 0; nt < 4; nt++) {
                    mma16816(c[mt][nt], ah[mt], bh[nt]);
                    mma16816(c[mt][nt], ah[mt], bl[nt]);
                    mma16816(c[mt][nt], al[mt], bh[nt]);
                }
        }
    };

    loadStage(0);
    storeStage(0);
    __syncthreads();
    for (int ch = 0; ch < 32; ch++) {
        const int buf = ch & 1;
        if (ch < 31) loadStage((ch + 1) * 32);
        compute(buf);
        if (ch < 31) storeStage(buf ^ 1);
        __syncthreads();
    }

#pragma unroll
    for (int mt = 0; mt < 4; mt++)
#pragma unroll
        for (int nt = 0; nt < 4; nt++) {
            const int dcol = wn + nt * 8 + q * 2;
            const int col = n0 + dcol;
#pragma unroll
            for (int hh = 0; hh < 2; hh++) {
                const int m = m0 + wm + mt * 16 + g + hh * 8;
                float v0 = c[mt][nt][hh * 2 + 0];
                float v1 = c[mt][nt][hh * 2 + 1];
                if (MODE == 0) {
                    const int bi = m >> 9, ns = m & 511, h = n0 >> 7;
                    float2 o;
                    o.x = (v0 + bias[col])     * g_gate2[bi * FEAT + col];
                    o.y = (v1 + bias[col + 1]) * g_gate2[bi * FEAT + col + 1];
                    *(float2*)&g_Q[(((size_t)bi * NH + h) * NUMS + ns) * HLEN + dcol] = o;
                } else {
                    float2 o;
                    o.x = fmaxf(v0 + bias[col], 0.f)     + res[(size_t)m * FEAT + col];
                    o.y = fmaxf(v1 + bias[col + 1], 0.f) + res[(size_t)m * FEAT + col + 1];
                    *(float2*)&Cout[(size_t)m * FEAT + col] = o;
                }
            }
        }
}

// ---------------------------------------------------------------- gate^2
__global__ void gate_kernel(const float* __restrict__ x2) {
    int b = blockIdx.y;
    int f = blockIdx.x * 256 + threadIdx.x;
    const float* p = x2 + (size_t)b * NUMS * FEAT + f;
    float s = 0.f;
#pragma unroll 8
    for (int n = 0; n < NUMS; n++) s += p[(size_t)n * FEAT];
    float g = s * (1.0f / NUMS);
    g_gate2[b * FEAT + f] = g * g * 0.08838834764831845f;  // 1/sqrt(128)
}

// ================================================================
// MMA attention: per (b, h, 64 Q-rows). S=QK^T (bf16 split), masked softmax,
// att out, O=att@V (bf16 split) -> g_Vp.
// smem bytes: S[64][520] f32 @0 (133120); Ah/Al u16 @133120/150528 (17408 ea);
//             Bh/Bl u16 @167936/186368 (18432 ea). total 204800.
#define ATT_SMEM 204800
__global__ __launch_bounds__(256) void attn_mma(
    const float* __restrict__ x1, const unsigned* __restrict__ mask,
    float* __restrict__ att_out)
{
    extern __shared__ char smc[];
    float*    S  = (float*)smc;                    // stride 520
    uint16_t* Ah = (uint16_t*)(smc + 133120);
    uint16_t* Al = (uint16_t*)(smc + 150528);
    uint16_t* Bh = (uint16_t*)(smc + 167936);
    uint16_t* Bl = (uint16_t*)(smc + 186368);

    const int tid = threadIdx.x;
    const int wid = tid >> 5, lane = tid & 31;
    const int g = lane >> 2, q = lane & 3;
    const int n0 = blockIdx.x * 64;
    const int h = blockIdx.y, b = blockIdx.z;
    const float* Kg = x1 + (size_t)b * NUMS * FEAT + h * HLEN;

    // ---- phase 0: Q tile -> Ah/Al (stride 136)
    {
        const float* Qg = g_Q + (((size_t)b * NH + h) * NUMS + n0) * HLEN;
        const int r = tid >> 2, kb = (tid & 3) * 32;
        const float* src = Qg + r * HLEN + kb;
#pragma unroll
        for (int i = 0; i < 32; i += 4) {
            uint2 hi, lo;
            cvt4(*(const float4*)(src + i), hi, lo);
            int off = r * 136 + kb + i;
            *(uint2*)&Ah[off] = hi;
            *(uint2*)&Al[off] = lo;
        }
    }

    // ---- phase 1: S = Q K^T in 64-col chunks
    const int wm2 = (wid >> 2) * 32, wn2 = (wid & 3) * 16;
    for (int mt = 0; mt < 8; mt++) {
        {   // K chunk rows mt*64.. -> Bh/Bl (stride 136)
            const int r = tid >> 2, kb = (tid & 3) * 32;
            const float* src = Kg + (size_t)(mt * 64 + r) * FEAT + kb;
#pragma unroll
            for (int i = 0; i < 32; i += 4) {
                uint2 hi, lo;
                cvt4(*(const float4*)(src + i), hi, lo);
                int off = r * 136 + kb + i;
                *(uint2*)&Bh[off] = hi;
                *(uint2*)&Bl[off] = lo;
            }
        }
        __syncthreads();
        float c1[2][2][4];
#pragma unroll
        for (int i = 0; i < 2; i++)
#pragma unroll
            for (int j = 0; j < 2; j++)
#pragma unroll
                for (int k = 0; k < 4; k++) c1[i][j][k] = 0.f;
#pragma unroll
        for (int ks = 0; ks < 8; ks++) {
            const int kb = ks * 16 + q * 2;
            uint32_t ah2[2][4], al2[2][4], bh2[2][2], bl2[2][2];
#pragma unroll
            for (int m2 = 0; m2 < 2; m2++) {
                int r0 = (wm2 + m2 * 16 + g) * 136 + kb;
                int r1 = r0 + 8 * 136;
                ah2[m2][0] = *(uint32_t*)&Ah[r0];
                ah2[m2][1] = *(uint32_t*)&Ah[r1];
                ah2[m2][2] = *(uint32_t*)&Ah[r0 + 8];
                ah2[m2][3] = *(uint32_t*)&Ah[r1 + 8];
                al2[m2][0] = *(uint32_t*)&Al[r0];
                al2[m2][1] = *(uint32_t*)&Al[r1];
                al2[m2][2] = *(uint32_t*)&Al[r0 + 8];
                al2[m2][3] = *(uint32_t*)&Al[r1 + 8];
            }
#pragma unroll
            for (int n2 = 0; n2 < 2; n2++) {
                int rb = (wn2 + n2 * 8 + g) * 136 + kb;
                bh2[n2][0] = *(uint32_t*)&Bh[rb];
                bh2[n2][1] = *(uint32_t*)&Bh[rb + 8];
                bl2[n2][0] = *(uint32_t*)&Bl[rb];
                bl2[n2][1] = *(uint32_t*)&Bl[rb + 8];
            }
#pragma unroll
            for (int m2 = 0; m2 < 2; m2++)
#pragma unroll
                for (int n2 = 0; n2 < 2; n2++) {
                    mma16816(c1[m2][n2], ah2[m2], bh2[n2]);
                    mma16816(c1[m2][n2], ah2[m2], bl2[n2]);
                    mma16816(c1[m2][n2], al2[m2], bh2[n2]);
                }
        }
#pragma unroll
        for (int m2 = 0; m2 < 2; m2++)
#pragma unroll
            for (int n2 = 0; n2 < 2; n2++) {
                const int row = wm2 + m2 * 16 + g;
                const int col = mt * 64 + wn2 + n2 * 8 + q * 2;
                S[row * 520 + col]           = c1[m2][n2][0];
                S[row * 520 + col + 1]       = c1[m2][n2][1];
                S[(row + 8) * 520 + col]     = c1[m2][n2][2];
                S[(row + 8) * 520 + col + 1] = c1[m2][n2][3];
            }
        __syncthreads();
    }

    // ---- phase 2: masked softmax (warp per row), write att, keep probs in S
    for (int r = wid; r < 64; r += 8) {
        float* Sr = S + r * 520;
        const unsigned* mrow = mask + (size_t)b * NUMS * NUMS + (size_t)(n0 + r) * NUMS;
        float mx = -1e30f;
        for (int c = lane; c < NUMS; c += 32) {
            float v = mrow[c] ? -1e9f : Sr[c];
            Sr[c] = v;
            mx = fmaxf(mx, v);
        }
#pragma unroll
        for (int o = 16; o; o >>= 1) mx = fmaxf(mx, __shfl_xor_sync(0xffffffffu, mx, o));
        float sum = 0.f;
        for (int c = lane; c < NUMS; c += 32) {
            float e = __expf(Sr[c] - mx);
            Sr[c] = e;
            sum += e;
        }
#pragma unroll
        for (int o = 16; o; o >>= 1) sum += __shfl_xor_sync(0xffffffffu, sum, o);
        float inv = 1.0f / sum;
        float* arow = att_out + (((size_t)b * NH + h) * NUMS + (n0 + r)) * NUMS;
        for (int c = lane; c < NUMS; c += 32) {
            float p = Sr[c] * inv;
            Sr[c] = p;
            arow[c] = p;
        }
    }
    __syncthreads();

    // ---- phase 3: O = att @ V in 64-k chunks (P stride 72, V^T stride 72)
    const int wm3 = (wid >> 1) * 16, wn3 = (wid & 1) * 64;
    float c3[8][4];
#pragma unroll
    for (int i = 0; i < 8; i++)
#pragma unroll
        for (int k = 0; k < 4; k++) c3[i][k] = 0.f;

    for (int kt = 0; kt < 8; kt++) {
        {   // P chunk: S[:, kt*64..] -> Ah/Al
            const int r = tid >> 2, cb = (tid & 3) * 16;
            const float* srow = &S[r * 520 + kt * 64 + cb];
#pragma unroll
            for (int i = 0; i < 16; i += 4) {
                uint2 hi, lo;
                cvt4(*(const float4*)(srow + i), hi, lo);
                int off = r * 72 + cb + i;
                *(uint2*)&Ah[off] = hi;
                *(uint2*)&Al[off] = lo;
            }
        }
        {   // V chunk transposed: Vh[d][kk] (stride 72)
            const int d = tid >> 1, kb2 = (tid & 1) * 32;
            const float* vcol = Kg + (size_t)(kt * 64 + kb2) * FEAT + d;
#pragma unroll 8
            for (int i = 0; i < 32; i++) {
                float f = vcol[(size_t)i * FEAT];
                float hf = hif(f);
                __nv_bfloat16 hb = __float2bfloat16_rn(f);
                __nv_bfloat16 lb = __float2bfloat16_rn(f - hf);
                Bh[d * 72 + kb2 + i] = *(uint16_t*)&hb;
                Bl[d * 72 + kb2 + i] = *(uint16_t*)&lb;
            }
        }
        __syncthreads();
#pragma unroll
        for (int ks = 0; ks < 4; ks++) {
            const int kb = ks * 16 + q * 2;
            int r0 = (wm3 + g) * 72 + kb;
            int r1 = r0 + 8 * 72;
            uint32_t pah[4] = {*(uint32_t*)&Ah[r0], *(uint32_t*)&Ah[r1],
                               *(uint32_t*)&Ah[r0 + 8], *(uint32_t*)&Ah[r1 + 8]};
            uint32_t pal[4] = {*(uint32_t*)&Al[r0], *(uint32_t*)&Al[r1],
                               *(uint32_t*)&Al[r0 + 8], *(uint32_t*)&Al[r1 + 8]};
#pragma unroll
            for (int nt = 0; nt < 8; nt++) {
                int rb = (wn3 + nt * 8 + g) * 72 + kb;
                uint32_t vbh[2] = {*(uint32_t*)&Bh[rb], *(uint32_t*)&Bh[rb + 8]};
                uint32_t vbl[2] = {*(uint32_t*)&Bl[rb], *(uint32_t*)&Bl[rb + 8]};
                mma16816(c3[nt], pah, vbh);
                mma16816(c3[nt], pah, vbl);
                mma16816(c3[nt], pal, vbh);
            }
        }
        __syncthreads();
    }

    // ---- write O -> g_Vp[b][n0+row][h*128+d]
    float* Vo = g_Vp + ((size_t)b * NUMS + n0) * FEAT + h * HLEN;
#pragma unroll
    for (int nt = 0; nt < 8; nt++) {
        const int d = wn3 + nt * 8 + q * 2;
        const int row = wm3 + g;
        float2 o0 = {c3[nt][0], c3[nt][1]};
        float2 o1 = {c3[nt][2], c3[nt][3]};
        *(float2*)&Vo[(size_t)row * FEAT + d]       = o0;
        *(float2*)&Vo[(size_t)(row + 8) * FEAT + d] = o1;
    }
}

// ----------------------------------------------------------------
extern "C" void kernel_launch(void* const* d_in, const int* in_sizes, int n_in,
                              void* d_out, int out_size) {
    const float*    x1   = (const float*)d_in[0];
    const float*    x2   = (const float*)d_in[1];
    const unsigned* mask = (const unsigned*)d_in[4];
    const float*    Wq   = (const float*)d_in[5];
    const float*    bq   = (const float*)d_in[6];
    const float*    Wl   = (const float*)d_in[7];
    const float*    bl   = (const float*)d_in[8];
    float* out = (float*)d_out;
    float* att = out + (size_t)BSZ * NUMS * FEAT;   // tuple: (xout, att)

    dim3 gg(FEAT / 256, BSZ);
    gate_kernel<<<gg, 256>>>(x2);

    const int GEMM_SMEM = 8 * PIECE * 2;  // 81920 B
    cudaFuncSetAttribute(gemm_mma<0>, cudaFuncAttributeMaxDynamicSharedMemorySize, GEMM_SMEM);
    cudaFuncSetAttribute(gemm_mma<1>, cudaFuncAttributeMaxDynamicSharedMemorySize, GEMM_SMEM);

    dim3 ggemm(FEAT / 128, (BSZ * NUMS) / 128);
    gemm_mma<0><<<ggemm, 256, GEMM_SMEM>>>(x1, Wq, bq, nullptr, nullptr);

    cudaFuncSetAttribute(attn_mma,
                         cudaFuncAttributeMaxDynamicSharedMemorySize, ATT_SMEM);
    dim3 ga(NUMS / 64, NH, BSZ);
    attn_mma<<<ga, 256, ATT_SMEM>>>(x1, mask, att);

    gemm_mma<1><<<ggemm, 256, GEMM_SMEM>>>(nullptr, Wl, bl, x1, out);
}

// round 7
// speedup vs baseline: 2.6616x; 1.3643x over previous
#include <cuda_runtime.h>
#include <cuda_bf16.h>
#include <cstdint>

#define BSZ  32
#define NUMS 512
#define FEAT 1024
#define NH   8
#define HLEN 128

#define NF ((size_t)BSZ * NUMS * FEAT)
// bf16 hi/lo scratch (allocation-free rule: __device__ globals)
__device__ __nv_bfloat16 g_x1h[NF], g_x1l[NF];              // x1 split, [b,n,f]
__device__ __nv_bfloat16 g_Qh [NF], g_Ql [NF];              // Q*(gate^2*scale) split, [b,h,n,d]
__device__ __nv_bfloat16 g_Oh [NF], g_Ol [NF];              // att@V split, [b,n,f]
__device__ __nv_bfloat16 g_Wqh[FEAT * FEAT], g_Wql[FEAT * FEAT];  // [h,f,d] flat
__device__ __nv_bfloat16 g_Wlh[FEAT * FEAT], g_Wll[FEAT * FEAT];  // [f,n]
__device__ float g_gate2[BSZ * FEAT];

// ---------------------------------------------------------------- helpers
__device__ __forceinline__ uint32_t smem_u32(const void* p) {
    uint32_t a;
    asm("{ .reg .u64 t; cvta.to.shared.u64 t, %1; cvt.u32.u64 %0, t; }" : "=r"(a) : "l"(p));
    return a;
}
__device__ __forceinline__ uint32_t pack2(float a, float b) {
    __nv_bfloat162 t = __floats2bfloat162_rn(a, b);
    return *(uint32_t*)&t;
}
__device__ __forceinline__ float hif(float f) {
    return __bfloat162float(__float2bfloat16_rn(f));
}
__device__ __forceinline__ void cvt4(float4 v, uint2& hi, uint2& lo) {
    float hx = hif(v.x), hy = hif(v.y), hz = hif(v.z), hw = hif(v.w);
    hi = make_uint2(pack2(v.x, v.y), pack2(v.z, v.w));
    lo = make_uint2(pack2(v.x - hx, v.y - hy), pack2(v.z - hz, v.w - hw));
}
__device__ __forceinline__ void mma16816(float* c, const uint32_t* a, const uint32_t* b) {
    asm volatile(
        "mma.sync.aligned.m16n8k16.row.col.f32.bf16.bf16.f32 "
        "{%0,%1,%2,%3}, {%4,%5,%6,%7}, {%8,%9}, {%0,%1,%2,%3};"
        : "+f"(c[0]), "+f"(c[1]), "+f"(c[2]), "+f"(c[3])
        : "r"(a[0]), "r"(a[1]), "r"(a[2]), "r"(a[3]), "r"(b[0]), "r"(b[1]));
}
__device__ __forceinline__ void ldm_x4(uint32_t* r, uint32_t sa) {
    asm volatile("ldmatrix.sync.aligned.m8n8.x4.shared.b16 {%0,%1,%2,%3}, [%4];"
        : "=r"(r[0]), "=r"(r[1]), "=r"(r[2]), "=r"(r[3]) : "r"(sa));
}
__device__ __forceinline__ void ldm_x4_t(uint32_t* r, uint32_t sa) {
    asm volatile("ldmatrix.sync.aligned.m8n8.x4.trans.shared.b16 {%0,%1,%2,%3}, [%4];"
        : "=r"(r[0]), "=r"(r[1]), "=r"(r[2]), "=r"(r[3]) : "r"(sa));
}
__device__ __forceinline__ void cpa16(uint32_t dst, const void* src) {
    asm volatile("cp.async.cg.shared.global [%0], [%1], 16;" :: "r"(dst), "l"(src));
}
#define CP_COMMIT() asm volatile("cp.async.commit_group;" ::: "memory")
#define CP_WAIT(n)  asm volatile("cp.async.wait_group %0;" :: "n"(n) : "memory")

// ---------------------------------------------------------------- split convert
__global__ void cvt_split(const float* __restrict__ src, __nv_bfloat16* __restrict__ h,
                          __nv_bfloat16* __restrict__ l, int n4) {
    int i = blockIdx.x * 256 + threadIdx.x;
    if (i < n4) {
        uint2 hi, lo;
        cvt4(((const float4*)src)[i], hi, lo);
        ((uint2*)h)[i] = hi;
        ((uint2*)l)[i] = lo;
    }
}

// ---------------------------------------------------------------- gate^2
__global__ void gate_kernel(const float* __restrict__ x2) {
    int b = blockIdx.y;
    int f = blockIdx.x * 256 + threadIdx.x;
    const float* p = x2 + (size_t)b * NUMS * FEAT + f;
    float s = 0.f;
#pragma unroll 8
    for (int n = 0; n < NUMS; n++) s += p[(size_t)n * FEAT];
    float g = s * (1.0f / NUMS);
    g_gate2[b * FEAT + f] = g * g * 0.08838834764831845f;  // 1/sqrt(128)
}

// ================================================================
// pipelined bf16 GEMM: C[16384,1024] = A @ B, 3-product hi/lo split
// smem per stage: Ah[128][40], Al, Bh[32][136], Bl  (bf16)
#define AELE 5120
#define BELE 4352
#define STAGE_E (2 * AELE + 2 * BELE)       // 18944 elems
#define GEMM_SMEM (4 * STAGE_E * 2)         // 151552 B

template <int MODE>
__global__ void __launch_bounds__(256) gemm_mma(
    const float* __restrict__ bias, const float* __restrict__ res,
    float* __restrict__ Cout)
{
    extern __shared__ __nv_bfloat16 smb[];
    const uint32_t sb = smem_u32(smb);
    const int tid = threadIdx.x;
    const int n0 = blockIdx.x * 128;
    const int m0 = blockIdx.y * 128;
    const int wid = tid >> 5, lane = tid & 31;
    const int wm = (wid >> 2) * 64, wn = (wid & 3) * 32;
    const int g = lane >> 2, q = lane & 3;

    const __nv_bfloat16* Ahg = MODE ? g_Oh : g_x1h;
    const __nv_bfloat16* Alg = MODE ? g_Ol : g_x1l;
    const __nv_bfloat16* Bhg = MODE ? g_Wlh + n0 : g_Wqh + (size_t)(n0 >> 7) * FEAT * HLEN;
    const __nv_bfloat16* Blg = MODE ? g_Wll + n0 : g_Wql + (size_t)(n0 >> 7) * FEAT * HLEN;
    const int ldbn = MODE ? FEAT : HLEN;

    const int ar = tid >> 1, ac = (tid & 1) * 16;
    const int br = tid >> 3, bc = (tid & 7) * 8;
    const size_t aoff = (size_t)(m0 + ar) * FEAT + ac;

    auto issue = [&](int slot, int k0) {
        uint32_t s = sb + slot * STAGE_E * 2;
        const __nv_bfloat16* ah = Ahg + aoff + k0;
        const __nv_bfloat16* al = Alg + aoff + k0;
        uint32_t da = s + (ar * 40 + ac) * 2;
        cpa16(da,                 ah);
        cpa16(da + 16,            ah + 8);
        cpa16(da + AELE * 2,      al);
        cpa16(da + AELE * 2 + 16, al + 8);
        const __nv_bfloat16* bh = Bhg + (size_t)(k0 + br) * ldbn + bc;
        const __nv_bfloat16* bl = Blg + (size_t)(k0 + br) * ldbn + bc;
        uint32_t db = s + 2 * AELE * 2 + (br * 136 + bc) * 2;
        cpa16(db,                  bh);
        cpa16(db + 128,            bh + 64);
        cpa16(db + BELE * 2,       bl);
        cpa16(db + BELE * 2 + 128, bl + 64);
        CP_COMMIT();
    };

    float c[4][4][4];
#pragma unroll
    for (int i = 0; i < 4; i++)
#pragma unroll
        for (int j = 0; j < 4; j++)
#pragma unroll
            for (int k = 0; k < 4; k++) c[i][j][k] = 0.f;

    const uint32_t lnA = ((lane & 15) * 40 + (lane >> 4) * 8) * 2;
    const uint32_t lnB = ((lane & 15) * 136 + (lane >> 4) * 8) * 2;

    issue(0, 0); issue(1, 32); issue(2, 64);

    for (int ch = 0; ch < 32; ch++) {
        if (ch < 29) { CP_WAIT(2); } else { CP_WAIT(0); }
        __syncthreads();
        if (ch <= 28) issue((ch + 3) & 3, (ch + 3) * 32);

        const int slot = ch & 3;
        uint32_t sA  = sb + slot * STAGE_E * 2;
        uint32_t sAl = sA + AELE * 2;
        uint32_t sB  = sA + 2 * AELE * 2;
        uint32_t sBl = sB + BELE * 2;
#pragma unroll
        for (int ks = 0; ks < 2; ks++) {
            uint32_t ah[4][4], al[4][4];
#pragma unroll
            for (int mt = 0; mt < 4; mt++) {
                uint32_t ro = ((wm + mt * 16) * 40 + ks * 16) * 2;
                ldm_x4(ah[mt], sA  + ro + lnA);
                ldm_x4(al[mt], sAl + ro + lnA);
            }
            uint32_t bfh[2][4], bfl[2][4];
#pragma unroll
            for (int bg = 0; bg < 2; bg++) {
                uint32_t ro = (ks * 16 * 136 + wn + bg * 16) * 2;
                ldm_x4_t(bfh[bg], sB  + ro + lnB);
                ldm_x4_t(bfl[bg], sBl + ro + lnB);
            }
#pragma unroll
            for (int mt = 0; mt < 4; mt++)
#pragma unroll
                for (int nt = 0; nt < 4; nt++) {
                    const uint32_t* bh = &bfh[nt >> 1][(nt & 1) * 2];
                    const uint32_t* bl = &bfl[nt >> 1][(nt & 1) * 2];
                    mma16816(c[mt][nt], ah[mt], bh);
                    mma16816(c[mt][nt], ah[mt], bl);
                    mma16816(c[mt][nt], al[mt], bh);
                }
        }
        __syncthreads();
    }

    // ---- epilogue
#pragma unroll
    for (int mt = 0; mt < 4; mt++)
#pragma unroll
        for (int nt = 0; nt < 4; nt++) {
            const int dcol = wn + nt * 8 + q * 2;
            const int col = n0 + dcol;
#pragma unroll
            for (int hh = 0; hh < 2; hh++) {
                const int m = m0 + wm + mt * 16 + g + hh * 8;
                float v0 = c[mt][nt][hh * 2 + 0];
                float v1 = c[mt][nt][hh * 2 + 1];
                if (MODE == 0) {
                    const int bi = m >> 9, ns = m & 511, h = n0 >> 7;
                    v0 = (v0 + bias[col])     * g_gate2[bi * FEAT + col];
                    v1 = (v1 + bias[col + 1]) * g_gate2[bi * FEAT + col + 1];
                    size_t o = (((size_t)bi * NH + h) * NUMS + ns) * HLEN + dcol;
                    *(uint32_t*)&g_Qh[o] = pack2(v0, v1);
                    *(uint32_t*)&g_Ql[o] = pack2(v0 - hif(v0), v1 - hif(v1));
                } else {
                    float2 o;
                    o.x = fmaxf(v0 + bias[col], 0.f)     + res[(size_t)m * FEAT + col];
                    o.y = fmaxf(v1 + bias[col + 1], 0.f) + res[(size_t)m * FEAT + col + 1];
                    *(float2*)&Cout[(size_t)m * FEAT + col] = o;
                }
            }
        }
}

// ================================================================
// attention per (b, h, 64 Q-rows): S=QK^T, masked softmax, att out, O=att@V.
// smem: S[64][520] f32 @0 (133120B)
//       Qh @133120 [64][136] (17408), Ql @150528   (phase3: Ph @133120 [64][40]=5120, Pl @138240)
//       KV dbuf @167936: slot*17408 { h:8704, l:8704 }  — K/V chunks [32][136]
#define ATT_SMEM 202752
__global__ void __launch_bounds__(256) attn_mma(
    const unsigned* __restrict__ mask, float* __restrict__ att_out)
{
    extern __shared__ char smc[];
    float* S = (float*)smc;
    const uint32_t sb = smem_u32(smc);
    const int tid = threadIdx.x;
    const int wid = tid >> 5, lane = tid & 31;
    const int g = lane >> 2, q = lane & 3;
    const int n0 = blockIdx.x * 64;
    const int h = blockIdx.y, b = blockIdx.z;

    const uint32_t lnB = ((lane & 15) * 136 + (lane >> 4) * 8) * 2;
    const uint32_t lnP = ((lane & 15) * 40  + (lane >> 4) * 8) * 2;

    // K/V chunk loader (32 seq rows from x1 head-slice)
    auto issueKV = [&](int ck, int slot) {
        uint32_t kb = sb + 167936 + slot * 17408;
        const int row = tid >> 3;
        const int bc = (tid & 7) * 8;
        size_t so = ((size_t)b * NUMS + ck * 32 + row) * FEAT + h * HLEN + bc;
        uint32_t d = kb + (row * 136 + bc) * 2;
        cpa16(d,              g_x1h + so);
        cpa16(d + 128,        g_x1h + so + 64);
        cpa16(d + 8704,       g_x1l + so);
        cpa16(d + 8704 + 128, g_x1l + so + 64);
        CP_COMMIT();
    };

    // ---- prologue: Q tile + first two K chunks
    {
        const int r = tid >> 2, cb = (tid & 3) * 32;
        size_t so = (((size_t)b * NH + h) * NUMS + n0 + r) * HLEN + cb;
        uint32_t d = sb + 133120 + (r * 136 + cb) * 2;
#pragma unroll
        for (int j = 0; j < 4; j++) {
            cpa16(d + j * 16,         g_Qh + so + j * 8);
            cpa16(d + 17408 + j * 16, g_Ql + so + j * 8);
        }
        CP_COMMIT();
    }
    issueKV(0, 0);
    issueKV(1, 1);

    // Q fragments -> registers (fixed for whole phase 1)
    const int wm2 = (wid >> 1) * 16, wn2 = (wid & 1) * 16;
    uint32_t qfh[8][4], qfl[8][4];
    CP_WAIT(2);
    __syncthreads();
#pragma unroll
    for (int ks = 0; ks < 8; ks++) {
        uint32_t ro = (wm2 * 136 + ks * 16) * 2;
        ldm_x4(qfh[ks], sb + 133120 + ro + lnB);
        ldm_x4(qfl[ks], sb + 150528 + ro + lnB);
    }

    // ---- phase 1: S = Q K^T, 16 chunks of 32 keys
    for (int mtc = 0; mtc < 16; mtc++) {
        if (mtc < 15) { CP_WAIT(1); } else { CP_WAIT(0); }
        __syncthreads();
        uint32_t kbh = sb + 167936 + (mtc & 1) * 17408;
        uint32_t kbl = kbh + 8704;
        float c1[2][4];
#pragma unroll
        for (int i = 0; i < 2; i++)
#pragma unroll
            for (int k = 0; k < 4; k++) c1[i][k] = 0.f;
#pragma unroll
        for (int ks = 0; ks < 8; ks++) {
            uint32_t kh[4], kl[4];
            uint32_t ro = (wn2 * 136 + ks * 16) * 2;
            ldm_x4(kh, kbh + ro + lnB);
            ldm_x4(kl, kbl + ro + lnB);
            uint32_t b0h[2] = {kh[0], kh[2]}, b1h[2] = {kh[1], kh[3]};
            uint32_t b0l[2] = {kl[0], kl[2]}, b1l[2] = {kl[1], kl[3]};
            mma16816(c1[0], qfh[ks], b0h);
            mma16816(c1[0], qfh[ks], b0l);
            mma16816(c1[0], qfl[ks], b0h);
            mma16816(c1[1], qfh[ks], b1h);
            mma16816(c1[1], qfh[ks], b1l);
            mma16816(c1[1], qfl[ks], b1h);
        }
#pragma unroll
        for (int nt = 0; nt < 2; nt++) {
            const int row = wm2 + g;
            const int col = mtc * 32 + wn2 + nt * 8 + q * 2;
            S[row * 520 + col]           = c1[nt][0];
            S[row * 520 + col + 1]       = c1[nt][1];
            S[(row + 8) * 520 + col]     = c1[nt][2];
            S[(row + 8) * 520 + col + 1] = c1[nt][3];
        }
        __syncthreads();
        if (mtc + 2 <= 15) issueKV(mtc + 2, mtc & 1);
    }

    // ---- phase 2: masked softmax; write att, keep probs in S
    for (int r = wid; r < 64; r += 8) {
        float* Sr = S + r * 520;
        const unsigned* mrow = mask + (size_t)b * NUMS * NUMS + (size_t)(n0 + r) * NUMS;
        float mx = -1e30f;
        for (int cc = lane; cc < NUMS; cc += 32) {
            float v = mrow[cc] ? -1e9f : Sr[cc];
            Sr[cc] = v;
            mx = fmaxf(mx, v);
        }
#pragma unroll
        for (int o = 16; o; o >>= 1) mx = fmaxf(mx, __shfl_xor_sync(0xffffffffu, mx, o));
        float sum = 0.f;
        for (int cc = lane; cc < NUMS; cc += 32) {
            float e = __expf(Sr[cc] - mx);
            Sr[cc] = e;
            sum += e;
        }
#pragma unroll
        for (int o = 16; o; o >>= 1) sum += __shfl_xor_sync(0xffffffffu, sum, o);
        float inv = 1.0f / sum;
        float* arow = att_out + (((size_t)b * NH + h) * NUMS + (n0 + r)) * NUMS;
        for (int cc = lane; cc < NUMS; cc += 32) {
            float p = Sr[cc] * inv;
            Sr[cc] = p;
            arow[cc] = p;
        }
    }
    __syncthreads();

    // ---- phase 3: O = att @ V, 16 chunks of 32 keys (V dbuf via cp.async)
    issueKV(0, 0);
    issueKV(1, 1);
    const int wm3 = (wid >> 1) * 16, wn3 = (wid & 1) * 64;
    float c3[8][4];
#pragma unroll
    for (int i = 0; i < 8; i++)
#pragma unroll
        for (int k = 0; k < 4; k++) c3[i][k] = 0.f;

    for (int kt = 0; kt < 16; kt++) {
        // convert P chunk (fp32 S -> bf16 hi/lo, stride 40)
        {
            const int r = tid >> 2, cb = (tid & 3) * 8;
            const float* sp = &S[r * 520 + kt * 32 + cb];
            uint2 h0, l0, h1, l1;
            cvt4(*(const float4*)sp,       h0, l0);
            cvt4(*(const float4*)(sp + 4), h1, l1);
            char* ph = smc + 133120 + (r * 40 + cb) * 2;
            char* pl = smc + 138240 + (r * 40 + cb) * 2;
            *(uint2*)ph       = h0;
            *(uint2*)(ph + 8) = h1;
            *(uint2*)pl       = l0;
            *(uint2*)(pl + 8) = l1;
        }
        if (kt < 15) { CP_WAIT(1); } else { CP_WAIT(0); }
        __syncthreads();
        uint32_t vbh = sb + 167936 + (kt & 1) * 17408;
        uint32_t vbl = vbh + 8704;
#pragma unroll
        for (int ks = 0; ks < 2; ks++) {
            uint32_t ph[4], pl[4];
            uint32_t ro = (wm3 * 40 + ks * 16) * 2;
            ldm_x4(ph, sb + 133120 + ro + lnP);
            ldm_x4(pl, sb + 138240 + ro + lnP);
#pragma unroll
            for (int vg = 0; vg < 4; vg++) {
                uint32_t vh[4], vl[4];
                uint32_t vo = (ks * 16 * 136 + wn3 + vg * 16) * 2;
                ldm_x4_t(vh, vbh + vo + lnB);
                ldm_x4_t(vl, vbl + vo + lnB);
#pragma unroll
                for (int hf = 0; hf < 2; hf++) {
                    float* cc = c3[vg * 2 + hf];
                    mma16816(cc, ph, &vh[hf * 2]);
                    mma16816(cc, ph, &vl[hf * 2]);
                    mma16816(cc, pl, &vh[hf * 2]);
                }
            }
        }
        __syncthreads();
        if (kt + 2 <= 15) issueKV(kt + 2, kt & 1);
    }

    // ---- epilogue: O -> g_Oh/g_Ol [b, n, f]
#pragma unroll
    for (int vg = 0; vg < 4; vg++)
#pragma unroll
        for (int hf = 0; hf < 2; hf++) {
            const float* cc = c3[vg * 2 + hf];
            const int d = wn3 + vg * 16 + hf * 8 + q * 2;
            const int row = wm3 + g;
            size_t o0 = ((size_t)b * NUMS + n0 + row) * FEAT + h * HLEN + d;
            size_t o1 = o0 + 8 * FEAT;
            *(uint32_t*)&g_Oh[o0] = pack2(cc[0], cc[1]);
            *(uint32_t*)&g_Ol[o0] = pack2(cc[0] - hif(cc[0]), cc[1] - hif(cc[1]));
            *(uint32_t*)&g_Oh[o1] = pack2(cc[2], cc[3]);
            *(uint32_t*)&g_Ol[o1] = pack2(cc[2] - hif(cc[2]), cc[3] - hif(cc[3]));
        }
}

// ----------------------------------------------------------------
extern "C" void kernel_launch(void* const* d_in, const int* in_sizes, int n_in,
                              void* d_out, int out_size) {
    const float*    x1   = (const float*)d_in[0];
    const float*    x2   = (const float*)d_in[1];
    const unsigned* mask = (const unsigned*)d_in[4];
    const float*    Wq   = (const float*)d_in[5];
    const float*    bq   = (const float*)d_in[6];
    const float*    Wl   = (const float*)d_in[7];
    const float*    bl   = (const float*)d_in[8];
    float* out = (float*)d_out;
    float* att = out + (size_t)BSZ * NUMS * FEAT;   // tuple: (xout, att)

    dim3 gg(FEAT / 256, BSZ);
    gate_kernel<<<gg, 256>>>(x2);

    // split converts
    { float* ph; cudaGetSymbolAddress((void**)&ph, g_x1h);
      float* pl; cudaGetSymbolAddress((void**)&pl, g_x1l);
      cvt_split<<<(int)(NF / 4 / 256), 256>>>(x1, (__nv_bfloat16*)ph, (__nv_bfloat16*)pl, (int)(NF / 4)); }
    { float* ph; cudaGetSymbolAddress((void**)&ph, g_Wqh);
      float* pl; cudaGetSymbolAddress((void**)&pl, g_Wql);
      cvt_split<<<FEAT * FEAT / 4 / 256, 256>>>(Wq, (__nv_bfloat16*)ph, (__nv_bfloat16*)pl, FEAT * FEAT / 4); }
    { float* ph; cudaGetSymbolAddress((void**)&ph, g_Wlh);
      float* pl; cudaGetSymbolAddress((void**)&pl, g_Wll);
      cvt_split<<<FEAT * FEAT / 4 / 256, 256>>>(Wl, (__nv_bfloat16*)ph, (__nv_bfloat16*)pl, FEAT * FEAT / 4); }

    cudaFuncSetAttribute(gemm_mma<0>, cudaFuncAttributeMaxDynamicSharedMemorySize, GEMM_SMEM);
    cudaFuncSetAttribute(gemm_mma<1>, cudaFuncAttributeMaxDynamicSharedMemorySize, GEMM_SMEM);
    cudaFuncSetAttribute(attn_mma,    cudaFuncAttributeMaxDynamicSharedMemorySize, ATT_SMEM);

    dim3 ggemm(FEAT / 128, (BSZ * NUMS) / 128);
    gemm_mma<0><<<ggemm, 256, GEMM_SMEM>>>(bq, nullptr, nullptr);

    dim3 ga(NUMS / 64, NH, BSZ);
    attn_mma<<<ga, 256, ATT_SMEM>>>(mask, att);

    gemm_mma<1><<<ggemm, 256, GEMM_SMEM>>>(bl, x1, out);
}

// round 8
// speedup vs baseline: 2.9211x; 1.0975x over previous
#include <cuda_runtime.h>
#include <cuda_bf16.h>
#include <cstdint>

#define BSZ  32
#define NUMS 512
#define FEAT 1024
#define NH   8
#define HLEN 128

#define NF ((size_t)BSZ * NUMS * FEAT)
// bf16 hi/lo scratch (allocation-free rule: __device__ globals)
__device__ __nv_bfloat16 g_x1h[NF], g_x1l[NF];              // x1 split, [b,n,f]
__device__ __nv_bfloat16 g_Qh [NF], g_Ql [NF];              // Q*(gate^2*scale) split, [b,h,n,d]
__device__ __nv_bfloat16 g_Oh [NF], g_Ol [NF];              // att@V split, [b,n,f]
__device__ __nv_bfloat16 g_Wqh[FEAT * FEAT], g_Wql[FEAT * FEAT];  // [h,f,d] flat
__device__ __nv_bfloat16 g_Wlh[FEAT * FEAT], g_Wll[FEAT * FEAT];  // [f,n]
__device__ float g_gate2[BSZ * FEAT];

// ---------------------------------------------------------------- helpers
__device__ __forceinline__ uint32_t smem_u32(const void* p) {
    uint32_t a;
    asm("{ .reg .u64 t; cvta.to.shared.u64 t, %1; cvt.u32.u64 %0, t; }" : "=r"(a) : "l"(p));
    return a;
}
__device__ __forceinline__ uint32_t pack2(float a, float b) {
    __nv_bfloat162 t = __floats2bfloat162_rn(a, b);
    return *(uint32_t*)&t;
}
__device__ __forceinline__ float hif(float f) {
    return __bfloat162float(__float2bfloat16_rn(f));
}
__device__ __forceinline__ void cvt4(float4 v, uint2& hi, uint2& lo) {
    float hx = hif(v.x), hy = hif(v.y), hz = hif(v.z), hw = hif(v.w);
    hi = make_uint2(pack2(v.x, v.y), pack2(v.z, v.w));
    lo = make_uint2(pack2(v.x - hx, v.y - hy), pack2(v.z - hz, v.w - hw));
}
__device__ __forceinline__ void mma16816(float* c, const uint32_t* a, const uint32_t* b) {
    asm volatile(
        "mma.sync.aligned.m16n8k16.row.col.f32.bf16.bf16.f32 "
        "{%0,%1,%2,%3}, {%4,%5,%6,%7}, {%8,%9}, {%0,%1,%2,%3};"
        : "+f"(c[0]), "+f"(c[1]), "+f"(c[2]), "+f"(c[3])
        : "r"(a[0]), "r"(a[1]), "r"(a[2]), "r"(a[3]), "r"(b[0]), "r"(b[1]));
}
__device__ __forceinline__ void ldm_x4(uint32_t* r, uint32_t sa) {
    asm volatile("ldmatrix.sync.aligned.m8n8.x4.shared.b16 {%0,%1,%2,%3}, [%4];"
        : "=r"(r[0]), "=r"(r[1]), "=r"(r[2]), "=r"(r[3]) : "r"(sa));
}
__device__ __forceinline__ void ldm_x4_t(uint32_t* r, uint32_t sa) {
    asm volatile("ldmatrix.sync.aligned.m8n8.x4.trans.shared.b16 {%0,%1,%2,%3}, [%4];"
        : "=r"(r[0]), "=r"(r[1]), "=r"(r[2]), "=r"(r[3]) : "r"(sa));
}
__device__ __forceinline__ void cpa16(uint32_t dst, const void* src) {
    asm volatile("cp.async.cg.shared.global [%0], [%1], 16;" :: "r"(dst), "l"(src));
}
#define CP_COMMIT() asm volatile("cp.async.commit_group;" ::: "memory")
#define CP_WAIT(n)  asm volatile("cp.async.wait_group %0;" :: "n"(n) : "memory")

// ---------------------------------------------------------------- split convert
__global__ void cvt_split(const float* __restrict__ src, __nv_bfloat16* __restrict__ h,
                          __nv_bfloat16* __restrict__ l, int n4) {
    int i = blockIdx.x * 256 + threadIdx.x;
    if (i < n4) {
        uint2 hi, lo;
        cvt4(((const float4*)src)[i], hi, lo);
        ((uint2*)h)[i] = hi;
        ((uint2*)l)[i] = lo;
    }
}

// ---------------------------------------------------------------- gate^2
__global__ void gate_kernel(const float* __restrict__ x2) {
    int b = blockIdx.y;
    int f = blockIdx.x * 256 + threadIdx.x;
    const float* p = x2 + (size_t)b * NUMS * FEAT + f;
    float s = 0.f;
#pragma unroll 8
    for (int n = 0; n < NUMS; n++) s += p[(size_t)n * FEAT];
    float g = s * (1.0f / NUMS);
    g_gate2[b * FEAT + f] = g * g * 0.08838834764831845f;  // 1/sqrt(128)
}

// ================================================================
// pipelined bf16 GEMM, 512 threads: C[16384,1024] = A @ B, 3-product split
// smem per stage: Ah[128][40], Al, Bh[32][136], Bl  (bf16)
#define AELE 5120
#define BELE 4352
#define STAGE_E (2 * AELE + 2 * BELE)       // 18944 elems
#define GEMM_SMEM (4 * STAGE_E * 2)         // 151552 B

template <int MODE>
__global__ void __launch_bounds__(512) gemm_mma(
    const float* __restrict__ bias, const float* __restrict__ res,
    float* __restrict__ Cout)
{
    extern __shared__ __nv_bfloat16 smb[];
    const uint32_t sb = smem_u32(smb);
    const int tid = threadIdx.x;
    const int n0 = blockIdx.x * 128;
    const int m0 = blockIdx.y * 128;
    const int wid = tid >> 5, lane = tid & 31;
    const int wm = (wid >> 2) * 32, wn = (wid & 3) * 32;
    const int g = lane >> 2, q = lane & 3;

    const __nv_bfloat16* Ahg = MODE ? g_Oh : g_x1h;
    const __nv_bfloat16* Alg = MODE ? g_Ol : g_x1l;
    const __nv_bfloat16* Bhg = MODE ? g_Wlh + n0 : g_Wqh + (size_t)(n0 >> 7) * FEAT * HLEN;
    const __nv_bfloat16* Blg = MODE ? g_Wll + n0 : g_Wql + (size_t)(n0 >> 7) * FEAT * HLEN;
    const int ldbn = MODE ? FEAT : HLEN;

    const int ar = tid >> 2, ac = (tid & 3) * 8;     // A: 128 rows x 4 8-col pieces
    const int br = tid >> 4, bc = (tid & 15) * 8;    // B: 32 rows x 16 8-col pieces
    const size_t aoff = (size_t)(m0 + ar) * FEAT + ac;

    auto issue = [&](int slot, int k0) {
        uint32_t s = sb + slot * STAGE_E * 2;
        uint32_t da = s + (ar * 40 + ac) * 2;
        cpa16(da,            Ahg + aoff + k0);
        cpa16(da + AELE * 2, Alg + aoff + k0);
        size_t bo = (size_t)(k0 + br) * ldbn + bc;
        uint32_t db = s + 2 * AELE * 2 + (br * 136 + bc) * 2;
        cpa16(db,            Bhg + bo);
        cpa16(db + BELE * 2, Blg + bo);
        CP_COMMIT();
    };

    float c[2][4][4];
#pragma unroll
    for (int i = 0; i < 2; i++)
#pragma unroll
        for (int j = 0; j < 4; j++)
#pragma unroll
            for (int k = 0; k < 4; k++) c[i][j][k] = 0.f;

    const uint32_t lnA = ((lane & 15) * 40 + (lane >> 4) * 8) * 2;
    const uint32_t lnB = ((lane & 15) * 136 + (lane >> 4) * 8) * 2;

    issue(0, 0); issue(1, 32); issue(2, 64);

    for (int ch = 0; ch < 32; ch++) {
        if (ch < 29) { CP_WAIT(2); } else { CP_WAIT(0); }
        __syncthreads();
        if (ch <= 28) issue((ch + 3) & 3, (ch + 3) * 32);

        const int slot = ch & 3;
        uint32_t sA  = sb + slot * STAGE_E * 2;
        uint32_t sAl = sA + AELE * 2;
        uint32_t sB  = sA + 2 * AELE * 2;
        uint32_t sBl = sB + BELE * 2;
#pragma unroll
        for (int ks = 0; ks < 2; ks++) {
            uint32_t ah[2][4], al[2][4];
#pragma unroll
            for (int mt = 0; mt < 2; mt++) {
                uint32_t ro = ((wm + mt * 16) * 40 + ks * 16) * 2;
                ldm_x4(ah[mt], sA  + ro + lnA);
                ldm_x4(al[mt], sAl + ro + lnA);
            }
            uint32_t bfh[2][4], bfl[2][4];
#pragma unroll
            for (int bg = 0; bg < 2; bg++) {
                uint32_t ro = (ks * 16 * 136 + wn + bg * 16) * 2;
                ldm_x4_t(bfh[bg], sB  + ro + lnB);
                ldm_x4_t(bfl[bg], sBl + ro + lnB);
            }
#pragma unroll
            for (int mt = 0; mt < 2; mt++)
#pragma unroll
                for (int nt = 0; nt < 4; nt++) {
                    const uint32_t* bh = &bfh[nt >> 1][(nt & 1) * 2];
                    const uint32_t* bl = &bfl[nt >> 1][(nt & 1) * 2];
                    mma16816(c[mt][nt], ah[mt], bh);
                    mma16816(c[mt][nt], ah[mt], bl);
                    mma16816(c[mt][nt], al[mt], bh);
                }
        }
        __syncthreads();
    }

    // ---- epilogue
#pragma unroll
    for (int mt = 0; mt < 2; mt++)
#pragma unroll
        for (int nt = 0; nt < 4; nt++) {
            const int dcol = wn + nt * 8 + q * 2;
            const int col = n0 + dcol;
#pragma unroll
            for (int hh = 0; hh < 2; hh++) {
                const int m = m0 + wm + mt * 16 + g + hh * 8;
                float v0 = c[mt][nt][hh * 2 + 0];
                float v1 = c[mt][nt][hh * 2 + 1];
                if (MODE == 0) {
                    const int bi = m >> 9, ns = m & 511, h = n0 >> 7;
                    v0 = (v0 + bias[col])     * g_gate2[bi * FEAT + col];
                    v1 = (v1 + bias[col + 1]) * g_gate2[bi * FEAT + col + 1];
                    size_t o = (((size_t)bi * NH + h) * NUMS + ns) * HLEN + dcol;
                    *(uint32_t*)&g_Qh[o] = pack2(v0, v1);
                    *(uint32_t*)&g_Ql[o] = pack2(v0 - hif(v0), v1 - hif(v1));
                } else {
                    float2 o;
                    o.x = fmaxf(v0 + bias[col], 0.f)     + res[(size_t)m * FEAT + col];
                    o.y = fmaxf(v1 + bias[col + 1], 0.f) + res[(size_t)m * FEAT + col + 1];
                    *(float2*)&Cout[(size_t)m * FEAT + col] = o;
                }
            }
        }
}

// ================================================================
// attention, 512 threads, per (b, h, 64 Q-rows).
// smem: S[64][520] f32 @0 (133120)
//       Ph @133120 [64][72] (9216), Pl @142336 (9216)
//       KV dbuf @151552: slot*34816 { h:17408, l:17408 } — 64-key chunks [64][136]
//       (Q staged through KV slot 0, then recycled)
#define ATT_SMEM 221184
__global__ void __launch_bounds__(512) attn_mma(
    const unsigned* __restrict__ mask, float* __restrict__ att_out)
{
    extern __shared__ char smc[];
    float* S = (float*)smc;
    const uint32_t sb = smem_u32(smc);
    const int tid = threadIdx.x;
    const int wid = tid >> 5, lane = tid & 31;
    const int g = lane >> 2, q = lane & 3;
    const int n0 = blockIdx.x * 64;
    const int h = blockIdx.y, b = blockIdx.z;

    const uint32_t lnB = ((lane & 15) * 136 + (lane >> 4) * 8) * 2;
    const uint32_t lnP = ((lane & 15) * 72  + (lane >> 4) * 8) * 2;
    const uint32_t KVB = sb + 151552;

    auto issueKV = [&](int ck, int slot) {
        const int row = tid >> 3, cb = (tid & 7) * 16;
        size_t so = ((size_t)b * NUMS + ck * 64 + row) * FEAT + h * HLEN + cb;
        uint32_t d = KVB + slot * 34816 + (row * 136 + cb) * 2;
        cpa16(d,              g_x1h + so);
        cpa16(d + 16,         g_x1h + so + 8);
        cpa16(d + 17408,      g_x1l + so);
        cpa16(d + 17408 + 16, g_x1l + so + 8);
        CP_COMMIT();
    };

    // ---- prologue: Q tile via KV slot 0
    {
        const int row = tid >> 3, cb = (tid & 7) * 16;
        size_t so = (((size_t)b * NH + h) * NUMS + n0 + row) * HLEN + cb;
        uint32_t d = KVB + (row * 136 + cb) * 2;
        cpa16(d,              g_Qh + so);
        cpa16(d + 16,         g_Qh + so + 8);
        cpa16(d + 17408,      g_Ql + so);
        cpa16(d + 17408 + 16, g_Ql + so + 8);
        CP_COMMIT();
    }
    CP_WAIT(0);
    __syncthreads();

    const int wm2 = (wid >> 2) * 16, wn2 = (wid & 3) * 16;
    uint32_t qfh[8][4], qfl[8][4];
#pragma unroll
    for (int ks = 0; ks < 8; ks++) {
        uint32_t ro = (wm2 * 136 + ks * 16) * 2;
        ldm_x4(qfh[ks], KVB + ro + lnB);
        ldm_x4(qfl[ks], KVB + 17408 + ro + lnB);
    }
    __syncthreads();          // all warps done reading Q from slot 0
    issueKV(0, 0);
    issueKV(1, 1);

    // ---- phase 1: S = Q K^T, 8 chunks of 64 keys
    for (int mtc = 0; mtc < 8; mtc++) {
        if (mtc < 7) { CP_WAIT(1); } else { CP_WAIT(0); }
        __syncthreads();
        uint32_t kbh = KVB + (mtc & 1) * 34816;
        uint32_t kbl = kbh + 17408;
        float c1[2][4];
#pragma unroll
        for (int i = 0; i < 2; i++)
#pragma unroll
            for (int k = 0; k < 4; k++) c1[i][k] = 0.f;
#pragma unroll
        for (int ks = 0; ks < 8; ks++) {
            uint32_t kh[4], kl[4];
            uint32_t ro = (wn2 * 136 + ks * 16) * 2;
            ldm_x4(kh, kbh + ro + lnB);
            ldm_x4(kl, kbl + ro + lnB);
            uint32_t b0h[2] = {kh[0], kh[2]}, b1h[2] = {kh[1], kh[3]};
            uint32_t b0l[2] = {kl[0], kl[2]}, b1l[2] = {kl[1], kl[3]};
            mma16816(c1[0], qfh[ks], b0h);
            mma16816(c1[0], qfh[ks], b0l);
            mma16816(c1[0], qfl[ks], b0h);
            mma16816(c1[1], qfh[ks], b1h);
            mma16816(c1[1], qfh[ks], b1l);
            mma16816(c1[1], qfl[ks], b1h);
        }
#pragma unroll
        for (int nt = 0; nt < 2; nt++) {
            const int row = wm2 + g;
            const int col = mtc * 64 + wn2 + nt * 8 + q * 2;
            S[row * 520 + col]           = c1[nt][0];
            S[row * 520 + col + 1]       = c1[nt][1];
            S[(row + 8) * 520 + col]     = c1[nt][2];
            S[(row + 8) * 520 + col + 1] = c1[nt][3];
        }
        __syncthreads();
        if (mtc + 2 <= 7) issueKV(mtc + 2, mtc & 1);
    }

    // ---- phase 2: masked softmax; write att, keep probs in S
    for (int r = wid; r < 64; r += 16) {
        float* Sr = S + r * 520;
        const unsigned* mrow = mask + (size_t)b * NUMS * NUMS + (size_t)(n0 + r) * NUMS;
        float mx = -1e30f;
        for (int cc = lane; cc < NUMS; cc += 32) {
            float v = mrow[cc] ? -1e9f : Sr[cc];
            Sr[cc] = v;
            mx = fmaxf(mx, v);
        }
#pragma unroll
        for (int o = 16; o; o >>= 1) mx = fmaxf(mx, __shfl_xor_sync(0xffffffffu, mx, o));
        float sum = 0.f;
        for (int cc = lane; cc < NUMS; cc += 32) {
            float e = __expf(Sr[cc] - mx);
            Sr[cc] = e;
            sum += e;
        }
#pragma unroll
        for (int o = 16; o; o >>= 1) sum += __shfl_xor_sync(0xffffffffu, sum, o);
        float inv = 1.0f / sum;
        float* arow = att_out + (((size_t)b * NH + h) * NUMS + (n0 + r)) * NUMS;
        for (int cc = lane; cc < NUMS; cc += 32) {
            float p = Sr[cc] * inv;
            Sr[cc] = p;
            arow[cc] = p;
        }
    }
    __syncthreads();

    // ---- phase 3: O = att @ V, 8 chunks of 64 keys
    issueKV(0, 0);
    issueKV(1, 1);
    const int wm3 = (wid >> 2) * 16, wn3 = (wid & 3) * 32;
    float c3[4][4];
#pragma unroll
    for (int i = 0; i < 4; i++)
#pragma unroll
        for (int k = 0; k < 4; k++) c3[i][k] = 0.f;

    for (int kt = 0; kt < 8; kt++) {
        {   // convert P chunk [64][64] -> Ph/Pl (stride 72)
            const int r = tid >> 3, cb = (tid & 7) * 8;
            const float* sp = &S[r * 520 + kt * 64 + cb];
            uint2 h0, l0, h1, l1;
            cvt4(*(const float4*)sp,       h0, l0);
            cvt4(*(const float4*)(sp + 4), h1, l1);
            char* ph = smc + 133120 + (r * 72 + cb) * 2;
            char* pl = smc + 142336 + (r * 72 + cb) * 2;
            *(uint2*)ph       = h0;
            *(uint2*)(ph + 8) = h1;
            *(uint2*)pl       = l0;
            *(uint2*)(pl + 8) = l1;
        }
        if (kt < 7) { CP_WAIT(1); } else { CP_WAIT(0); }
        __syncthreads();
        uint32_t vbh = KVB + (kt & 1) * 34816;
        uint32_t vbl = vbh + 17408;
#pragma unroll
        for (int ks = 0; ks < 4; ks++) {
            uint32_t ph[4], pl[4];
            uint32_t ro = (wm3 * 72 + ks * 16) * 2;
            ldm_x4(ph, sb + 133120 + ro + lnP);
            ldm_x4(pl, sb + 142336 + ro + lnP);
#pragma unroll
            for (int vg = 0; vg < 2; vg++) {
                uint32_t vh[4], vl[4];
                uint32_t vo = (ks * 16 * 136 + wn3 + vg * 16) * 2;
                ldm_x4_t(vh, vbh + vo + lnB);
                ldm_x4_t(vl, vbl + vo + lnB);
#pragma unroll
                for (int hf = 0; hf < 2; hf++) {
                    float* cc = c3[vg * 2 + hf];
                    mma16816(cc, ph, &vh[hf * 2]);
                    mma16816(cc, ph, &vl[hf * 2]);
                    mma16816(cc, pl, &vh[hf * 2]);
                }
            }
        }
        __syncthreads();
        if (kt + 2 <= 7) issueKV(kt + 2, kt & 1);
    }

    // ---- epilogue: O -> g_Oh/g_Ol [b, n, f]
#pragma unroll
    for (int vg = 0; vg < 2; vg++)
#pragma unroll
        for (int hf = 0; hf < 2; hf++) {
            const float* cc = c3[vg * 2 + hf];
            const int d = wn3 + vg * 16 + hf * 8 + q * 2;
            const int row = wm3 + g;
            size_t o0 = ((size_t)b * NUMS + n0 + row) * FEAT + h * HLEN + d;
            size_t o1 = o0 + 8 * FEAT;
            *(uint32_t*)&g_Oh[o0] = pack2(cc[0], cc[1]);
            *(uint32_t*)&g_Ol[o0] = pack2(cc[0] - hif(cc[0]), cc[1] - hif(cc[1]));
            *(uint32_t*)&g_Oh[o1] = pack2(cc[2], cc[3]);
            *(uint32_t*)&g_Ol[o1] = pack2(cc[2] - hif(cc[2]), cc[3] - hif(cc[3]));
        }
}

// ----------------------------------------------------------------
extern "C" void kernel_launch(void* const* d_in, const int* in_sizes, int n_in,
                              void* d_out, int out_size) {
    const float*    x1   = (const float*)d_in[0];
    const float*    x2   = (const float*)d_in[1];
    const unsigned* mask = (const unsigned*)d_in[4];
    const float*    Wq   = (const float*)d_in[5];
    const float*    bq   = (const float*)d_in[6];
    const float*    Wl   = (const float*)d_in[7];
    const float*    bl   = (const float*)d_in[8];
    float* out = (float*)d_out;
    float* att = out + (size_t)BSZ * NUMS * FEAT;   // tuple: (xout, att)

    dim3 gg(FEAT / 256, BSZ);
    gate_kernel<<<gg, 256>>>(x2);

    { float* ph; cudaGetSymbolAddress((void**)&ph, g_x1h);
      float* pl; cudaGetSymbolAddress((void**)&pl, g_x1l);
      cvt_split<<<(int)(NF / 4 / 256), 256>>>(x1, (__nv_bfloat16*)ph, (__nv_bfloat16*)pl, (int)(NF / 4)); }
    { float* ph; cudaGetSymbolAddress((void**)&ph, g_Wqh);
      float* pl; cudaGetSymbolAddress((void**)&pl, g_Wql);
      cvt_split<<<FEAT * FEAT / 4 / 256, 256>>>(Wq, (__nv_bfloat16*)ph, (__nv_bfloat16*)pl, FEAT * FEAT / 4); }
    { float* ph; cudaGetSymbolAddress((void**)&ph, g_Wlh);
      float* pl; cudaGetSymbolAddress((void**)&pl, g_Wll);
      cvt_split<<<FEAT * FEAT / 4 / 256, 256>>>(Wl, (__nv_bfloat16*)ph, (__nv_bfloat16*)pl, FEAT * FEAT / 4); }

    cudaFuncSetAttribute(gemm_mma<0>, cudaFuncAttributeMaxDynamicSharedMemorySize, GEMM_SMEM);
    cudaFuncSetAttribute(gemm_mma<1>, cudaFuncAttributeMaxDynamicSharedMemorySize, GEMM_SMEM);
    cudaFuncSetAttribute(attn_mma,    cudaFuncAttributeMaxDynamicSharedMemorySize, ATT_SMEM);

    dim3 ggemm(FEAT / 128, (BSZ * NUMS) / 128);
    gemm_mma<0><<<ggemm, 512, GEMM_SMEM>>>(bq, nullptr, nullptr);

    dim3 ga(NUMS / 64, NH, BSZ);
    attn_mma<<<ga, 512, ATT_SMEM>>>(mask, att);

    gemm_mma<1><<<ggemm, 512, GEMM_SMEM>>>(bl, x1, out);
}

// round 9
// speedup vs baseline: 5.6764x; 1.9432x over previous
#include <cuda_runtime.h>
#include <cuda_bf16.h>
#include <cstdint>

#define BSZ  32
#define NUMS 512
#define FEAT 1024
#define NH   8
#define HLEN 128

#define NF ((size_t)BSZ * NUMS * FEAT)
// bf16 scratch (allocation-free rule: __device__ globals)
__device__ __nv_bfloat16 g_x1h[NF];                 // x1 bf16, [b,n,f]
__device__ __nv_bfloat16 g_Qh [NF];                 // Q*(gate^2*scale) bf16, [b,h,n,d]
__device__ __nv_bfloat16 g_Oh [NF];                 // att@V bf16, [b,n,f]
__device__ __nv_bfloat16 g_Wqh[FEAT * FEAT];        // [h,f,d] flat
__device__ __nv_bfloat16 g_Wlh[FEAT * FEAT];        // [f,n]
__device__ float g_gate2[BSZ * FEAT];

// ---------------------------------------------------------------- helpers
__device__ __forceinline__ uint32_t smem_u32(const void* p) {
    uint32_t a;
    asm("{ .reg .u64 t; cvta.to.shared.u64 t, %1; cvt.u32.u64 %0, t; }" : "=r"(a) : "l"(p));
    return a;
}
__device__ __forceinline__ uint32_t pack2(float a, float b) {
    __nv_bfloat162 t = __floats2bfloat162_rn(a, b);
    return *(uint32_t*)&t;
}
__device__ __forceinline__ void mma16816(float* c, const uint32_t* a, const uint32_t* b) {
    asm volatile(
        "mma.sync.aligned.m16n8k16.row.col.f32.bf16.bf16.f32 "
        "{%0,%1,%2,%3}, {%4,%5,%6,%7}, {%8,%9}, {%0,%1,%2,%3};"
        : "+f"(c[0]), "+f"(c[1]), "+f"(c[2]), "+f"(c[3])
        : "r"(a[0]), "r"(a[1]), "r"(a[2]), "r"(a[3]), "r"(b[0]), "r"(b[1]));
}
__device__ __forceinline__ void ldm_x4(uint32_t* r, uint32_t sa) {
    asm volatile("ldmatrix.sync.aligned.m8n8.x4.shared.b16 {%0,%1,%2,%3}, [%4];"
        : "=r"(r[0]), "=r"(r[1]), "=r"(r[2]), "=r"(r[3]) : "r"(sa));
}
__device__ __forceinline__ void ldm_x4_t(uint32_t* r, uint32_t sa) {
    asm volatile("ldmatrix.sync.aligned.m8n8.x4.trans.shared.b16 {%0,%1,%2,%3}, [%4];"
        : "=r"(r[0]), "=r"(r[1]), "=r"(r[2]), "=r"(r[3]) : "r"(sa));
}
__device__ __forceinline__ void cpa16(uint32_t dst, const void* src) {
    asm volatile("cp.async.cg.shared.global [%0], [%1], 16;" :: "r"(dst), "l"(src));
}
#define CP_COMMIT() asm volatile("cp.async.commit_group;" ::: "memory")
#define CP_WAIT(n)  asm volatile("cp.async.wait_group %0;" :: "n"(n) : "memory")

// ---------------------------------------------------------------- convert to bf16
__global__ void cvt_h(const float* __restrict__ src, __nv_bfloat16* __restrict__ h, int n4) {
    int i = blockIdx.x * 256 + threadIdx.x;
    if (i < n4) {
        float4 v = ((const float4*)src)[i];
        ((uint2*)h)[i] = make_uint2(pack2(v.x, v.y), pack2(v.z, v.w));
    }
}

// ---------------------------------------------------------------- gate^2
__global__ void gate_kernel(const float* __restrict__ x2) {
    int b = blockIdx.y;
    int f = blockIdx.x * 256 + threadIdx.x;
    const float* p = x2 + (size_t)b * NUMS * FEAT + f;
    float s = 0.f;
#pragma unroll 8
    for (int n = 0; n < NUMS; n++) s += p[(size_t)n * FEAT];
    float g = s * (1.0f / NUMS);
    g_gate2[b * FEAT + f] = g * g * 0.08838834764831845f;  // 1/sqrt(128)
}

// ================================================================
// pipelined bf16 GEMM, 512 threads, single product.
// smem per stage: A[128][40], B[32][136] (bf16)
#define AELE 5120
#define BELE 4352
#define STAGE_E (AELE + BELE)               // 9472 elems
#define GEMM_SMEM (4 * STAGE_E * 2)         // 75776 B

template <int MODE>
__global__ void __launch_bounds__(512) gemm_mma(
    const float* __restrict__ bias, const float* __restrict__ res,
    float* __restrict__ Cout)
{
    extern __shared__ __nv_bfloat16 smb[];
    const uint32_t sb = smem_u32(smb);
    const int tid = threadIdx.x;
    const int n0 = blockIdx.x * 128;
    const int m0 = blockIdx.y * 128;
    const int wid = tid >> 5, lane = tid & 31;
    const int wm = (wid >> 2) * 32, wn = (wid & 3) * 32;
    const int g = lane >> 2, q = lane & 3;

    const __nv_bfloat16* Ahg = MODE ? g_Oh : g_x1h;
    const __nv_bfloat16* Bhg = MODE ? g_Wlh + n0 : g_Wqh + (size_t)(n0 >> 7) * FEAT * HLEN;
    const int ldbn = MODE ? FEAT : HLEN;

    const int ar = tid >> 2, ac = (tid & 3) * 8;     // A: 128 rows x 4 8-col pieces
    const int br = tid >> 4, bc = (tid & 15) * 8;    // B: 32 rows x 16 8-col pieces
    const size_t aoff = (size_t)(m0 + ar) * FEAT + ac;

    auto issue = [&](int slot, int k0) {
        uint32_t s = sb + slot * STAGE_E * 2;
        cpa16(s + (ar * 40 + ac) * 2, Ahg + aoff + k0);
        cpa16(s + AELE * 2 + (br * 136 + bc) * 2, Bhg + (size_t)(k0 + br) * ldbn + bc);
        CP_COMMIT();
    };

    float c[2][4][4];
#pragma unroll
    for (int i = 0; i < 2; i++)
#pragma unroll
        for (int j = 0; j < 4; j++)
#pragma unroll
            for (int k = 0; k < 4; k++) c[i][j][k] = 0.f;

    const uint32_t lnA = ((lane & 15) * 40 + (lane >> 4) * 8) * 2;
    const uint32_t lnB = ((lane & 15) * 136 + (lane >> 4) * 8) * 2;

    issue(0, 0); issue(1, 32); issue(2, 64);

    for (int ch = 0; ch < 32; ch++) {
        if (ch < 29) { CP_WAIT(2); } else { CP_WAIT(0); }
        __syncthreads();
        if (ch <= 28) issue((ch + 3) & 3, (ch + 3) * 32);

        const int slot = ch & 3;
        uint32_t sA = sb + slot * STAGE_E * 2;
        uint32_t sB = sA + AELE * 2;
#pragma unroll
        for (int ks = 0; ks < 2; ks++) {
            uint32_t ah[2][4];
#pragma unroll
            for (int mt = 0; mt < 2; mt++)
                ldm_x4(ah[mt], sA + ((wm + mt * 16) * 40 + ks * 16) * 2 + lnA);
            uint32_t bfh[2][4];
#pragma unroll
            for (int bg = 0; bg < 2; bg++)
                ldm_x4_t(bfh[bg], sB + (ks * 16 * 136 + wn + bg * 16) * 2 + lnB);
#pragma unroll
            for (int mt = 0; mt < 2; mt++)
#pragma unroll
                for (int nt = 0; nt < 4; nt++)
                    mma16816(c[mt][nt], ah[mt], &bfh[nt >> 1][(nt & 1) * 2]);
        }
        __syncthreads();
    }

    // ---- epilogue
#pragma unroll
    for (int mt = 0; mt < 2; mt++)
#pragma unroll
        for (int nt = 0; nt < 4; nt++) {
            const int dcol = wn + nt * 8 + q * 2;
            const int col = n0 + dcol;
#pragma unroll
            for (int hh = 0; hh < 2; hh++) {
                const int m = m0 + wm + mt * 16 + g + hh * 8;
                float v0 = c[mt][nt][hh * 2 + 0];
                float v1 = c[mt][nt][hh * 2 + 1];
                if (MODE == 0) {
                    const int bi = m >> 9, ns = m & 511, h = n0 >> 7;
                    v0 = (v0 + bias[col])     * g_gate2[bi * FEAT + col];
                    v1 = (v1 + bias[col + 1]) * g_gate2[bi * FEAT + col + 1];
                    size_t o = (((size_t)bi * NH + h) * NUMS + ns) * HLEN + dcol;
                    *(uint32_t*)&g_Qh[o] = pack2(v0, v1);
                } else {
                    float2 o;
                    o.x = fmaxf(v0 + bias[col], 0.f)     + res[(size_t)m * FEAT + col];
                    o.y = fmaxf(v1 + bias[col + 1], 0.f) + res[(size_t)m * FEAT + col + 1];
                    *(float2*)&Cout[(size_t)m * FEAT + col] = o;
                }
            }
        }
}

// ================================================================
// attention, 512 threads, single bf16 product, per (b, h, 64 Q-rows).
// smem: S[64][520] f32 @0 (133120); P bf16 @133120 [64][72] (9216);
//       KV dbuf @142336: slot*17408 — 64-key chunks [64][136] bf16.
#define ATT_SMEM 177152
__global__ void __launch_bounds__(512) attn_mma(
    const unsigned* __restrict__ mask, float* __restrict__ att_out)
{
    extern __shared__ char smc[];
    float* S = (float*)smc;
    const uint32_t sb = smem_u32(smc);
    const int tid = threadIdx.x;
    const int wid = tid >> 5, lane = tid & 31;
    const int g = lane >> 2, q = lane & 3;
    const int n0 = blockIdx.x * 64;
    const int h = blockIdx.y, b = blockIdx.z;

    const uint32_t lnB = ((lane & 15) * 136 + (lane >> 4) * 8) * 2;
    const uint32_t lnP = ((lane & 15) * 72  + (lane >> 4) * 8) * 2;
    const uint32_t PB  = sb + 133120;
    const uint32_t KVB = sb + 142336;

    auto issueKV = [&](int ck, int slot) {
        const int row = tid >> 3, cb = (tid & 7) * 16;
        size_t so = ((size_t)b * NUMS + ck * 64 + row) * FEAT + h * HLEN + cb;
        uint32_t d = KVB + slot * 17408 + (row * 136 + cb) * 2;
        cpa16(d,      g_x1h + so);
        cpa16(d + 16, g_x1h + so + 8);
        CP_COMMIT();
    };

    // ---- prologue: Q tile via KV slot 0
    {
        const int row = tid >> 3, cb = (tid & 7) * 16;
        size_t so = (((size_t)b * NH + h) * NUMS + n0 + row) * HLEN + cb;
        uint32_t d = KVB + (row * 136 + cb) * 2;
        cpa16(d,      g_Qh + so);
        cpa16(d + 16, g_Qh + so + 8);
        CP_COMMIT();
    }
    CP_WAIT(0);
    __syncthreads();

    const int wm2 = (wid >> 2) * 16, wn2 = (wid & 3) * 16;
    uint32_t qfh[8][4];
#pragma unroll
    for (int ks = 0; ks < 8; ks++)
        ldm_x4(qfh[ks], KVB + (wm2 * 136 + ks * 16) * 2 + lnB);
    __syncthreads();          // all warps done reading Q from slot 0
    issueKV(0, 0);
    issueKV(1, 1);

    // ---- phase 1: S = Q K^T, 8 chunks of 64 keys
    for (int mtc = 0; mtc < 8; mtc++) {
        if (mtc < 7) { CP_WAIT(1); } else { CP_WAIT(0); }
        __syncthreads();
        uint32_t kbh = KVB + (mtc & 1) * 17408;
        float c1[2][4];
#pragma unroll
        for (int i = 0; i < 2; i++)
#pragma unroll
            for (int k = 0; k < 4; k++) c1[i][k] = 0.f;
#pragma unroll
        for (int ks = 0; ks < 8; ks++) {
            uint32_t kh[4];
            ldm_x4(kh, kbh + (wn2 * 136 + ks * 16) * 2 + lnB);
            uint32_t b0h[2] = {kh[0], kh[2]}, b1h[2] = {kh[1], kh[3]};
            mma16816(c1[0], qfh[ks], b0h);
            mma16816(c1[1], qfh[ks], b1h);
        }
#pragma unroll
        for (int nt = 0; nt < 2; nt++) {
            const int row = wm2 + g;
            const int col = mtc * 64 + wn2 + nt * 8 + q * 2;
            S[row * 520 + col]           = c1[nt][0];
            S[row * 520 + col + 1]       = c1[nt][1];
            S[(row + 8) * 520 + col]     = c1[nt][2];
            S[(row + 8) * 520 + col + 1] = c1[nt][3];
        }
        __syncthreads();
        if (mtc + 2 <= 7) issueKV(mtc + 2, mtc & 1);
    }

    // ---- phase 2: masked softmax; write att, keep probs in S
    for (int r = wid; r < 64; r += 16) {
        float* Sr = S + r * 520;
        const unsigned* mrow = mask + (size_t)b * NUMS * NUMS + (size_t)(n0 + r) * NUMS;
        float mx = -1e30f;
        for (int cc = lane; cc < NUMS; cc += 32) {
            float v = mrow[cc] ? -1e9f : Sr[cc];
            Sr[cc] = v;
            mx = fmaxf(mx, v);
        }
#pragma unroll
        for (int o = 16; o; o >>= 1) mx = fmaxf(mx, __shfl_xor_sync(0xffffffffu, mx, o));
        float sum = 0.f;
        for (int cc = lane; cc < NUMS; cc += 32) {
            float e = __expf(Sr[cc] - mx);
            Sr[cc] = e;
            sum += e;
        }
#pragma unroll
        for (int o = 16; o; o >>= 1) sum += __shfl_xor_sync(0xffffffffu, sum, o);
        float inv = 1.0f / sum;
        float* arow = att_out + (((size_t)b * NH + h) * NUMS + (n0 + r)) * NUMS;
        for (int cc = lane; cc < NUMS; cc += 32) {
            float p = Sr[cc] * inv;
            Sr[cc] = p;
            arow[cc] = p;
        }
    }
    __syncthreads();

    // ---- phase 3: O = att @ V, 8 chunks of 64 keys
    issueKV(0, 0);
    issueKV(1, 1);
    const int wm3 = (wid >> 2) * 16, wn3 = (wid & 3) * 32;
    float c3[4][4];
#pragma unroll
    for (int i = 0; i < 4; i++)
#pragma unroll
        for (int k = 0; k < 4; k++) c3[i][k] = 0.f;

    for (int kt = 0; kt < 8; kt++) {
        {   // convert P chunk [64][64] -> bf16 (stride 72)
            const int r = tid >> 3, cb = (tid & 7) * 8;
            const float* sp = &S[r * 520 + kt * 64 + cb];
            float4 v0 = *(const float4*)sp;
            float4 v1 = *(const float4*)(sp + 4);
            *(uint2*)(smc + 133120 + (r * 72 + cb) * 2) =
                make_uint2(pack2(v0.x, v0.y), pack2(v0.z, v0.w));
            *(uint2*)(smc + 133120 + (r * 72 + cb) * 2 + 8) =
                make_uint2(pack2(v1.x, v1.y), pack2(v1.z, v1.w));
        }
        if (kt < 7) { CP_WAIT(1); } else { CP_WAIT(0); }
        __syncthreads();
        uint32_t vbh = KVB + (kt & 1) * 17408;
#pragma unroll
        for (int ks = 0; ks < 4; ks++) {
            uint32_t ph[4];
            ldm_x4(ph, PB + (wm3 * 72 + ks * 16) * 2 + lnP);
#pragma unroll
            for (int vg = 0; vg < 2; vg++) {
                uint32_t vh[4];
                ldm_x4_t(vh, vbh + (ks * 16 * 136 + wn3 + vg * 16) * 2 + lnB);
                mma16816(c3[vg * 2 + 0], ph, &vh[0]);
                mma16816(c3[vg * 2 + 1], ph, &vh[2]);
            }
        }
        __syncthreads();
        if (kt + 2 <= 7) issueKV(kt + 2, kt & 1);
    }

    // ---- epilogue: O -> g_Oh [b, n, f] (bf16)
#pragma unroll
    for (int vg = 0; vg < 2; vg++)
#pragma unroll
        for (int hf = 0; hf < 2; hf++) {
            const float* cc = c3[vg * 2 + hf];
            const int d = wn3 + vg * 16 + hf * 8 + q * 2;
            const int row = wm3 + g;
            size_t o0 = ((size_t)b * NUMS + n0 + row) * FEAT + h * HLEN + d;
            size_t o1 = o0 + 8 * FEAT;
            *(uint32_t*)&g_Oh[o0] = pack2(cc[0], cc[1]);
            *(uint32_t*)&g_Oh[o1] = pack2(cc[2], cc[3]);
        }
}

// ----------------------------------------------------------------
extern "C" void kernel_launch(void* const* d_in, const int* in_sizes, int n_in,
                              void* d_out, int out_size) {
    const float*    x1   = (const float*)d_in[0];
    const float*    x2   = (const float*)d_in[1];
    const unsigned* mask = (const unsigned*)d_in[4];
    const float*    Wq   = (const float*)d_in[5];
    const float*    bq   = (const float*)d_in[6];
    const float*    Wl   = (const float*)d_in[7];
    const float*    bl   = (const float*)d_in[8];
    float* out = (float*)d_out;
    float* att = out + (size_t)BSZ * NUMS * FEAT;   // tuple: (xout, att)

    dim3 gg(FEAT / 256, BSZ);
    gate_kernel<<<gg, 256>>>(x2);

    { void* p; cudaGetSymbolAddress(&p, g_x1h);
      cvt_h<<<(int)(NF / 4 / 256), 256>>>(x1, (__nv_bfloat16*)p, (int)(NF / 4)); }
    { void* p; cudaGetSymbolAddress(&p, g_Wqh);
      cvt_h<<<FEAT * FEAT / 4 / 256, 256>>>(Wq, (__nv_bfloat16*)p, FEAT * FEAT / 4); }
    { void* p; cudaGetSymbolAddress(&p, g_Wlh);
      cvt_h<<<FEAT * FEAT / 4 / 256, 256>>>(Wl, (__nv_bfloat16*)p, FEAT * FEAT / 4); }

    cudaFuncSetAttribute(gemm_mma<0>, cudaFuncAttributeMaxDynamicSharedMemorySize, GEMM_SMEM);
    cudaFuncSetAttribute(gemm_mma<1>, cudaFuncAttributeMaxDynamicSharedMemorySize, GEMM_SMEM);
    cudaFuncSetAttribute(attn_mma,    cudaFuncAttributeMaxDynamicSharedMemorySize, ATT_SMEM);

    dim3 ggemm(FEAT / 128, (BSZ * NUMS) / 128);
    gemm_mma<0><<<ggemm, 512, GEMM_SMEM>>>(bq, nullptr, nullptr);

    dim3 ga(NUMS / 64, NH, BSZ);
    attn_mma<<<ga, 512, ATT_SMEM>>>(mask, att);

    gemm_mma<1><<<ggemm, 512, GEMM_SMEM>>>(bl, x1, out);
}

// round 10
// speedup vs baseline: 5.7841x; 1.0190x over previous
#include <cuda_runtime.h>
#include <cuda_bf16.h>
#include <cstdint>

#define BSZ  32
#define NUMS 512
#define FEAT 1024
#define NH   8
#define HLEN 128

#define NF ((size_t)BSZ * NUMS * FEAT)
// bf16 scratch (allocation-free rule: __device__ globals)
__device__ __nv_bfloat16 g_x1h[NF];                 // x1 bf16, [b,n,f]
__device__ __nv_bfloat16 g_Qh [NF];                 // Q*(gate^2*scale) bf16, [b,h,n,d]
__device__ __nv_bfloat16 g_Oh [NF];                 // att@V bf16, [b,n,f]
__device__ __nv_bfloat16 g_Wqh[FEAT * FEAT];        // [h,f,d] flat
__device__ __nv_bfloat16 g_Wlh[FEAT * FEAT];        // [f,n]
__device__ float g_gate2[BSZ * FEAT];

// ---------------------------------------------------------------- helpers
__device__ __forceinline__ uint32_t smem_u32(const void* p) {
    uint32_t a;
    asm("{ .reg .u64 t; cvta.to.shared.u64 t, %1; cvt.u32.u64 %0, t; }" : "=r"(a) : "l"(p));
    return a;
}
__device__ __forceinline__ uint32_t pack2(float a, float b) {
    __nv_bfloat162 t = __floats2bfloat162_rn(a, b);
    return *(uint32_t*)&t;
}
__device__ __forceinline__ void mma16816(float* c, const uint32_t* a, const uint32_t* b) {
    asm volatile(
        "mma.sync.aligned.m16n8k16.row.col.f32.bf16.bf16.f32 "
        "{%0,%1,%2,%3}, {%4,%5,%6,%7}, {%8,%9}, {%0,%1,%2,%3};"
        : "+f"(c[0]), "+f"(c[1]), "+f"(c[2]), "+f"(c[3])
        : "r"(a[0]), "r"(a[1]), "r"(a[2]), "r"(a[3]), "r"(b[0]), "r"(b[1]));
}
__device__ __forceinline__ void ldm_x4(uint32_t* r, uint32_t sa) {
    asm volatile("ldmatrix.sync.aligned.m8n8.x4.shared.b16 {%0,%1,%2,%3}, [%4];"
        : "=r"(r[0]), "=r"(r[1]), "=r"(r[2]), "=r"(r[3]) : "r"(sa));
}
__device__ __forceinline__ void ldm_x4_t(uint32_t* r, uint32_t sa) {
    asm volatile("ldmatrix.sync.aligned.m8n8.x4.trans.shared.b16 {%0,%1,%2,%3}, [%4];"
        : "=r"(r[0]), "=r"(r[1]), "=r"(r[2]), "=r"(r[3]) : "r"(sa));
}
__device__ __forceinline__ void cpa16(uint32_t dst, const void* src) {
    asm volatile("cp.async.cg.shared.global [%0], [%1], 16;" :: "r"(dst), "l"(src));
}
#define CP_COMMIT() asm volatile("cp.async.commit_group;" ::: "memory")
#define CP_WAIT(n)  asm volatile("cp.async.wait_group %0;" :: "n"(n) : "memory")

// ---------------------------------------------------------------- convert to bf16
__global__ void cvt_h(const float* __restrict__ src, __nv_bfloat16* __restrict__ h, int n4) {
    int i = blockIdx.x * 256 + threadIdx.x;
    if (i < n4) {
        float4 v = ((const float4*)src)[i];
        ((uint2*)h)[i] = make_uint2(pack2(v.x, v.y), pack2(v.z, v.w));
    }
}

// ---------------------------------------------------------------- gate^2
__global__ void gate_kernel(const float* __restrict__ x2) {
    int b = blockIdx.y;
    int f = blockIdx.x * 256 + threadIdx.x;
    const float* p = x2 + (size_t)b * NUMS * FEAT + f;
    float s = 0.f;
#pragma unroll 8
    for (int n = 0; n < NUMS; n++) s += p[(size_t)n * FEAT];
    float g = s * (1.0f / NUMS);
    g_gate2[b * FEAT + f] = g * g * 0.08838834764831845f;  // 1/sqrt(128)
}

// ================================================================
// pipelined bf16 GEMM, 512 threads, k-chunk 64, 3 stages, 1 sync/iter.
// stage: A[128][72] + B[64][136] bf16 = 35840 B
#define AELE 9216
#define BELE 8704
#define STAGE_E (AELE + BELE)               // 17920 elems
#define GEMM_SMEM (3 * STAGE_E * 2)         // 107520 B

template <int MODE>
__global__ void __launch_bounds__(512) gemm_mma(
    const float* __restrict__ bias, const float* __restrict__ res,
    float* __restrict__ Cout)
{
    extern __shared__ __nv_bfloat16 smb[];
    const uint32_t sb = smem_u32(smb);
    const int tid = threadIdx.x;
    const int n0 = blockIdx.x * 128;
    const int m0 = blockIdx.y * 128;
    const int wid = tid >> 5, lane = tid & 31;
    const int wm = (wid >> 2) * 32, wn = (wid & 3) * 32;
    const int g = lane >> 2, q = lane & 3;

    const __nv_bfloat16* Ahg = MODE ? g_Oh : g_x1h;
    const __nv_bfloat16* Bhg = MODE ? g_Wlh + n0 : g_Wqh + (size_t)(n0 >> 7) * FEAT * HLEN;
    const int ldbn = MODE ? FEAT : HLEN;

    const int ar = tid >> 2, ac = (tid & 3) * 16;    // A: 128 rows x 4 16-col pieces
    const int br = tid >> 3, bc = (tid & 7) * 16;    // B: 64 rows x 8 16-col pieces
    const size_t aoff = (size_t)(m0 + ar) * FEAT + ac;

    auto issue = [&](int slot, int k0) {
        uint32_t s = sb + slot * STAGE_E * 2;
        const __nv_bfloat16* ap = Ahg + aoff + k0;
        uint32_t da = s + (ar * 72 + ac) * 2;
        cpa16(da,      ap);
        cpa16(da + 16, ap + 8);
        const __nv_bfloat16* bp = Bhg + (size_t)(k0 + br) * ldbn + bc;
        uint32_t db = s + AELE * 2 + (br * 136 + bc) * 2;
        cpa16(db,      bp);
        cpa16(db + 16, bp + 8);
        CP_COMMIT();
    };

    float c[2][4][4];
#pragma unroll
    for (int i = 0; i < 2; i++)
#pragma unroll
        for (int j = 0; j < 4; j++)
#pragma unroll
            for (int k = 0; k < 4; k++) c[i][j][k] = 0.f;

    const uint32_t lnA = ((lane & 15) * 72 + (lane >> 4) * 8) * 2;
    const uint32_t lnB = ((lane & 15) * 136 + (lane >> 4) * 8) * 2;

    issue(0, 0);
    issue(1, 64);

    for (int ch = 0; ch < 16; ch++) {
        if (ch < 15) { CP_WAIT(1); } else { CP_WAIT(0); }
        __syncthreads();
        if (ch + 2 <= 15) issue((ch + 2) % 3, (ch + 2) * 64);

        uint32_t sA = sb + (ch % 3) * STAGE_E * 2;
        uint32_t sB = sA + AELE * 2;
#pragma unroll
        for (int ks = 0; ks < 4; ks++) {
            uint32_t ah[2][4];
#pragma unroll
            for (int mt = 0; mt < 2; mt++)
                ldm_x4(ah[mt], sA + ((wm + mt * 16) * 72 + ks * 16) * 2 + lnA);
            uint32_t bfh[2][4];
#pragma unroll
            for (int bg = 0; bg < 2; bg++)
                ldm_x4_t(bfh[bg], sB + (ks * 16 * 136 + wn + bg * 16) * 2 + lnB);
#pragma unroll
            for (int mt = 0; mt < 2; mt++)
#pragma unroll
                for (int nt = 0; nt < 4; nt++)
                    mma16816(c[mt][nt], ah[mt], &bfh[nt >> 1][(nt & 1) * 2]);
        }
    }

    // ---- epilogue
#pragma unroll
    for (int mt = 0; mt < 2; mt++)
#pragma unroll
        for (int nt = 0; nt < 4; nt++) {
            const int dcol = wn + nt * 8 + q * 2;
            const int col = n0 + dcol;
#pragma unroll
            for (int hh = 0; hh < 2; hh++) {
                const int m = m0 + wm + mt * 16 + g + hh * 8;
                float v0 = c[mt][nt][hh * 2 + 0];
                float v1 = c[mt][nt][hh * 2 + 1];
                if (MODE == 0) {
                    const int bi = m >> 9, ns = m & 511, h = n0 >> 7;
                    v0 = (v0 + bias[col])     * g_gate2[bi * FEAT + col];
                    v1 = (v1 + bias[col + 1]) * g_gate2[bi * FEAT + col + 1];
                    size_t o = (((size_t)bi * NH + h) * NUMS + ns) * HLEN + dcol;
                    *(uint32_t*)&g_Qh[o] = pack2(v0, v1);
                } else {
                    float2 o;
                    o.x = fmaxf(v0 + bias[col], 0.f)     + res[(size_t)m * FEAT + col];
                    o.y = fmaxf(v1 + bias[col + 1], 0.f) + res[(size_t)m * FEAT + col + 1];
                    *(float2*)&Cout[(size_t)m * FEAT + col] = o;
                }
            }
        }
}

// ================================================================
// attention, 512 threads, per (b, h, 64 Q-rows); 1 sync/iter.
// smem: S[64][520] f32 @0 (133120); P dbuf @133120 2x[64][72] (18432);
//       KV 3 slots @151552: [64][136] bf16 x 17408 B.
#define PBOFF 133120
#define KVOFF 151552
#define ATT_SMEM 203776
__global__ void __launch_bounds__(512) attn_mma(
    const unsigned* __restrict__ mask, float* __restrict__ att_out)
{
    extern __shared__ char smc[];
    float* S = (float*)smc;
    const uint32_t sb = smem_u32(smc);
    const int tid = threadIdx.x;
    const int wid = tid >> 5, lane = tid & 31;
    const int g = lane >> 2, q = lane & 3;
    const int n0 = blockIdx.x * 64;
    const int h = blockIdx.y, b = blockIdx.z;

    const uint32_t lnB = ((lane & 15) * 136 + (lane >> 4) * 8) * 2;
    const uint32_t lnP = ((lane & 15) * 72  + (lane >> 4) * 8) * 2;
    const uint32_t KVB = sb + KVOFF;
    const unsigned* mbase = mask + (size_t)b * NUMS * NUMS;

    auto issueKV = [&](int ck, int slot) {
        const int row = tid >> 3, cb = (tid & 7) * 16;
        size_t so = ((size_t)b * NUMS + ck * 64 + row) * FEAT + h * HLEN + cb;
        uint32_t d = KVB + slot * 17408 + (row * 136 + cb) * 2;
        cpa16(d,      g_x1h + so);
        cpa16(d + 16, g_x1h + so + 8);
        CP_COMMIT();
    };

    // ---- prologue: Q via KV slot 2, K chunks 0,1 into slots 0,1
    {
        const int row = tid >> 3, cb = (tid & 7) * 16;
        size_t so = (((size_t)b * NH + h) * NUMS + n0 + row) * HLEN + cb;
        uint32_t d = KVB + 2 * 17408 + (row * 136 + cb) * 2;
        cpa16(d,      g_Qh + so);
        cpa16(d + 16, g_Qh + so + 8);
        CP_COMMIT();
    }
    issueKV(0, 0);
    issueKV(1, 1);
    CP_WAIT(2);              // Q done (chunks 0,1 may be outstanding)
    __syncthreads();

    const int wm2 = (wid >> 2) * 16, wn2 = (wid & 3) * 16;
    uint32_t qfh[8][4];
#pragma unroll
    for (int ks = 0; ks < 8; ks++)
        ldm_x4(qfh[ks], KVB + 2 * 17408 + (wm2 * 136 + ks * 16) * 2 + lnB);

    // ---- phase 1: S = Q K^T, 8 chunks of 64 keys; mask folded into store
    for (int mtc = 0; mtc < 8; mtc++) {
        if (mtc < 7) { CP_WAIT(1); } else { CP_WAIT(0); }
        __syncthreads();                         // also covers Q-frag reads (iter 0)
        if (mtc + 2 <= 7) issueKV(mtc + 2, (mtc + 2) % 3);

        uint32_t kbh = KVB + (mtc % 3) * 17408;
        float c1[2][4];
#pragma unroll
        for (int i = 0; i < 2; i++)
#pragma unroll
            for (int k = 0; k < 4; k++) c1[i][k] = 0.f;
#pragma unroll
        for (int ks = 0; ks < 8; ks++) {
            uint32_t kh[4];
            ldm_x4(kh, kbh + (wn2 * 136 + ks * 16) * 2 + lnB);
            uint32_t b0h[2] = {kh[0], kh[2]}, b1h[2] = {kh[1], kh[3]};
            mma16816(c1[0], qfh[ks], b0h);
            mma16816(c1[1], qfh[ks], b1h);
        }
#pragma unroll
        for (int nt = 0; nt < 2; nt++) {
            const int row = wm2 + g;
            const int col = mtc * 64 + wn2 + nt * 8 + q * 2;
            uint2 m0v = *(const uint2*)&mbase[(size_t)(n0 + row) * NUMS + col];
            uint2 m1v = *(const uint2*)&mbase[(size_t)(n0 + row + 8) * NUMS + col];
            S[row * 520 + col]           = m0v.x ? -1e9f : c1[nt][0];
            S[row * 520 + col + 1]       = m0v.y ? -1e9f : c1[nt][1];
            S[(row + 8) * 520 + col]     = m1v.x ? -1e9f : c1[nt][2];
            S[(row + 8) * 520 + col + 1] = m1v.y ? -1e9f : c1[nt][3];
        }
    }
    __syncthreads();                             // S complete
    issueKV(0, 0);                               // prefetch V chunks over softmax
    issueKV(1, 1);

    // ---- phase 2: softmax (mask already applied); write att, probs stay in S
    for (int r = wid; r < 64; r += 16) {
        float* Sr = S + r * 520;
        float mx = -1e30f;
        for (int cc = lane; cc < NUMS; cc += 32) mx = fmaxf(mx, Sr[cc]);
#pragma unroll
        for (int o = 16; o; o >>= 1) mx = fmaxf(mx, __shfl_xor_sync(0xffffffffu, mx, o));
        float sum = 0.f;
        for (int cc = lane; cc < NUMS; cc += 32) {
            float e = __expf(Sr[cc] - mx);
            Sr[cc] = e;
            sum += e;
        }
#pragma unroll
        for (int o = 16; o; o >>= 1) sum += __shfl_xor_sync(0xffffffffu, sum, o);
        float inv = 1.0f / sum;
        float* arow = att_out + (((size_t)b * NH + h) * NUMS + (n0 + r)) * NUMS;
        for (int cc = lane; cc < NUMS; cc += 32) {
            float p = Sr[cc] * inv;
            Sr[cc] = p;
            arow[cc] = p;
        }
    }
    __syncthreads();                             // probs visible to all

    // ---- phase 3: O = att @ V, 8 chunks of 64 keys; P double-buffered
    const int wm3 = (wid >> 2) * 16, wn3 = (wid & 3) * 32;
    float c3[4][4];
#pragma unroll
    for (int i = 0; i < 4; i++)
#pragma unroll
        for (int k = 0; k < 4; k++) c3[i][k] = 0.f;

    for (int kt = 0; kt < 8; kt++) {
        {   // convert P chunk [64][64] -> bf16 into Pbuf[kt&1] (stride 72)
            const int r = tid >> 3, cb = (tid & 7) * 8;
            const float* sp = &S[r * 520 + kt * 64 + cb];
            float4 v0 = *(const float4*)sp;
            float4 v1 = *(const float4*)(sp + 4);
            char* pd = smc + PBOFF + (kt & 1) * 9216 + (r * 72 + cb) * 2;
            *(uint2*)pd       = make_uint2(pack2(v0.x, v0.y), pack2(v0.z, v0.w));
            *(uint2*)(pd + 8) = make_uint2(pack2(v1.x, v1.y), pack2(v1.z, v1.w));
        }
        if (kt < 7) { CP_WAIT(1); } else { CP_WAIT(0); }
        __syncthreads();
        if (kt + 2 <= 7) issueKV(kt + 2, (kt + 2) % 3);

        uint32_t vbh = KVB + (kt % 3) * 17408;
        uint32_t pB  = sb + PBOFF + (kt & 1) * 9216;
#pragma unroll
        for (int ks = 0; ks < 4; ks++) {
            uint32_t ph[4];
            ldm_x4(ph, pB + (wm3 * 72 + ks * 16) * 2 + lnP);
#pragma unroll
            for (int vg = 0; vg < 2; vg++) {
                uint32_t vh[4];
                ldm_x4_t(vh, vbh + (ks * 16 * 136 + wn3 + vg * 16) * 2 + lnB);
                mma16816(c3[vg * 2 + 0], ph, &vh[0]);
                mma16816(c3[vg * 2 + 1], ph, &vh[2]);
            }
        }
    }

    // ---- epilogue: O -> g_Oh [b, n, f] (bf16)
#pragma unroll
    for (int vg = 0; vg < 2; vg++)
#pragma unroll
        for (int hf = 0; hf < 2; hf++) {
            const float* cc = c3[vg * 2 + hf];
            const int d = wn3 + vg * 16 + hf * 8 + q * 2;
            const int row = wm3 + g;
            size_t o0 = ((size_t)b * NUMS + n0 + row) * FEAT + h * HLEN + d;
            size_t o1 = o0 + 8 * FEAT;
            *(uint32_t*)&g_Oh[o0] = pack2(cc[0], cc[1]);
            *(uint32_t*)&g_Oh[o1] = pack2(cc[2], cc[3]);
        }
}

// ----------------------------------------------------------------
extern "C" void kernel_launch(void* const* d_in, const int* in_sizes, int n_in,
                              void* d_out, int out_size) {
    const float*    x1   = (const float*)d_in[0];
    const float*    x2   = (const float*)d_in[1];
    const unsigned* mask = (const unsigned*)d_in[4];
    const float*    Wq   = (const float*)d_in[5];
    const float*    bq   = (const float*)d_in[6];
    const float*    Wl   = (const float*)d_in[7];
    const float*    bl   = (const float*)d_in[8];
    float* out = (float*)d_out;
    float* att = out + (size_t)BSZ * NUMS * FEAT;   // tuple: (xout, att)

    dim3 gg(FEAT / 256, BSZ);
    gate_kernel<<<gg, 256>>>(x2);

    { void* p; cudaGetSymbolAddress(&p, g_x1h);
      cvt_h<<<(int)(NF / 4 / 256), 256>>>(x1, (__nv_bfloat16*)p, (int)(NF / 4)); }
    { void* p; cudaGetSymbolAddress(&p, g_Wqh);
      cvt_h<<<FEAT * FEAT / 4 / 256, 256>>>(Wq, (__nv_bfloat16*)p, FEAT * FEAT / 4); }
    { void* p; cudaGetSymbolAddress(&p, g_Wlh);
      cvt_h<<<FEAT * FEAT / 4 / 256, 256>>>(Wl, (__nv_bfloat16*)p, FEAT * FEAT / 4); }

    cudaFuncSetAttribute(gemm_mma<0>, cudaFuncAttributeMaxDynamicSharedMemorySize, GEMM_SMEM);
    cudaFuncSetAttribute(gemm_mma<1>, cudaFuncAttributeMaxDynamicSharedMemorySize, GEMM_SMEM);
    cudaFuncSetAttribute(attn_mma,    cudaFuncAttributeMaxDynamicSharedMemorySize, ATT_SMEM);

    dim3 ggemm(FEAT / 128, (BSZ * NUMS) / 128);
    gemm_mma<0><<<ggemm, 512, GEMM_SMEM>>>(bq, nullptr, nullptr);

    dim3 ga(NUMS / 64, NH, BSZ);
    attn_mma<<<ga, 512, ATT_SMEM>>>(mask, att);

    gemm_mma<1><<<ggemm, 512, GEMM_SMEM>>>(bl, x1, out);
}

// round 11
// speedup vs baseline: 6.2765x; 1.0851x over previous
#include <cuda_runtime.h>
#include <cuda_bf16.h>
#include <cstdint>

#define BSZ  32
#define NUMS 512
#define FEAT 1024
#define NH   8
#define HLEN 128

#define NF ((size_t)BSZ * NUMS * FEAT)
// bf16 scratch (allocation-free rule: __device__ globals)
__device__ __nv_bfloat16 g_x1h[NF];                 // x1 bf16, [b,n,f]
__device__ __nv_bfloat16 g_Qh [NF];                 // Q*(gate^2*scale) bf16, [b,h,n,d]
__device__ __nv_bfloat16 g_Oh [NF];                 // att@V bf16, [b,n,f]
__device__ __nv_bfloat16 g_Wqh[FEAT * FEAT];        // [h,f,d] flat
__device__ __nv_bfloat16 g_Wlh[FEAT * FEAT];        // [f,n]
__device__ float g_gate2[BSZ * FEAT];

// ---------------------------------------------------------------- helpers
__device__ __forceinline__ uint32_t smem_u32(const void* p) {
    uint32_t a;
    asm("{ .reg .u64 t; cvta.to.shared.u64 t, %1; cvt.u32.u64 %0, t; }" : "=r"(a) : "l"(p));
    return a;
}
__device__ __forceinline__ uint32_t pack2(float a, float b) {
    __nv_bfloat162 t = __floats2bfloat162_rn(a, b);
    return *(uint32_t*)&t;
}
__device__ __forceinline__ void mma16816(float* c, const uint32_t* a, const uint32_t* b) {
    asm volatile(
        "mma.sync.aligned.m16n8k16.row.col.f32.bf16.bf16.f32 "
        "{%0,%1,%2,%3}, {%4,%5,%6,%7}, {%8,%9}, {%0,%1,%2,%3};"
        : "+f"(c[0]), "+f"(c[1]), "+f"(c[2]), "+f"(c[3])
        : "r"(a[0]), "r"(a[1]), "r"(a[2]), "r"(a[3]), "r"(b[0]), "r"(b[1]));
}
__device__ __forceinline__ void ldm_x4(uint32_t* r, uint32_t sa) {
    asm volatile("ldmatrix.sync.aligned.m8n8.x4.shared.b16 {%0,%1,%2,%3}, [%4];"
        : "=r"(r[0]), "=r"(r[1]), "=r"(r[2]), "=r"(r[3]) : "r"(sa));
}
__device__ __forceinline__ void ldm_x4_t(uint32_t* r, uint32_t sa) {
    asm volatile("ldmatrix.sync.aligned.m8n8.x4.trans.shared.b16 {%0,%1,%2,%3}, [%4];"
        : "=r"(r[0]), "=r"(r[1]), "=r"(r[2]), "=r"(r[3]) : "r"(sa));
}
__device__ __forceinline__ void cpa16(uint32_t dst, const void* src) {
    asm volatile("cp.async.cg.shared.global [%0], [%1], 16;" :: "r"(dst), "l"(src));
}
#define CP_COMMIT() asm volatile("cp.async.commit_group;" ::: "memory")
#define CP_WAIT(n)  asm volatile("cp.async.wait_group %0;" :: "n"(n) : "memory")

// ---------------------------------------------------------------- convert to bf16
__global__ void cvt_h(const float* __restrict__ src, __nv_bfloat16* __restrict__ h, int n4) {
    int i = blockIdx.x * 256 + threadIdx.x;
    if (i < n4) {
        float4 v = ((const float4*)src)[i];
        ((uint2*)h)[i] = make_uint2(pack2(v.x, v.y), pack2(v.z, v.w));
    }
}

// ---------------------------------------------------------------- gate^2
__global__ void gate_kernel(const float* __restrict__ x2) {
    int b = blockIdx.y;
    int f = blockIdx.x * 256 + threadIdx.x;
    const float* p = x2 + (size_t)b * NUMS * FEAT + f;
    float s = 0.f;
#pragma unroll 8
    for (int n = 0; n < NUMS; n++) s += p[(size_t)n * FEAT];
    float g = s * (1.0f / NUMS);
    g_gate2[b * FEAT + f] = g * g * 0.08838834764831845f;  // 1/sqrt(128)
}

// ================================================================
// pipelined bf16 GEMM (unchanged from R10-passing): k-chunk 64, 3 stages.
#define AELE 9216
#define BELE 8704
#define STAGE_E (AELE + BELE)
#define GEMM_SMEM (3 * STAGE_E * 2)         // 107520 B

template <int MODE>
__global__ void __launch_bounds__(512) gemm_mma(
    const float* __restrict__ bias, const float* __restrict__ res,
    float* __restrict__ Cout)
{
    extern __shared__ __nv_bfloat16 smb[];
    const uint32_t sb = smem_u32(smb);
    const int tid = threadIdx.x;
    const int n0 = blockIdx.x * 128;
    const int m0 = blockIdx.y * 128;
    const int wid = tid >> 5, lane = tid & 31;
    const int wm = (wid >> 2) * 32, wn = (wid & 3) * 32;
    const int g = lane >> 2, q = lane & 3;

    const __nv_bfloat16* Ahg = MODE ? g_Oh : g_x1h;
    const __nv_bfloat16* Bhg = MODE ? g_Wlh + n0 : g_Wqh + (size_t)(n0 >> 7) * FEAT * HLEN;
    const int ldbn = MODE ? FEAT : HLEN;

    const int ar = tid >> 2, ac = (tid & 3) * 16;
    const int br = tid >> 3, bc = (tid & 7) * 16;
    const size_t aoff = (size_t)(m0 + ar) * FEAT + ac;

    auto issue = [&](int slot, int k0) {
        uint32_t s = sb + slot * STAGE_E * 2;
        const __nv_bfloat16* ap = Ahg + aoff + k0;
        uint32_t da = s + (ar * 72 + ac) * 2;
        cpa16(da,      ap);
        cpa16(da + 16, ap + 8);
        const __nv_bfloat16* bp = Bhg + (size_t)(k0 + br) * ldbn + bc;
        uint32_t db = s + AELE * 2 + (br * 136 + bc) * 2;
        cpa16(db,      bp);
        cpa16(db + 16, bp + 8);
        CP_COMMIT();
    };

    float c[2][4][4];
#pragma unroll
    for (int i = 0; i < 2; i++)
#pragma unroll
        for (int j = 0; j < 4; j++)
#pragma unroll
            for (int k = 0; k < 4; k++) c[i][j][k] = 0.f;

    const uint32_t lnA = ((lane & 15) * 72 + (lane >> 4) * 8) * 2;
    const uint32_t lnB = ((lane & 15) * 136 + (lane >> 4) * 8) * 2;

    issue(0, 0);
    issue(1, 64);

    for (int ch = 0; ch < 16; ch++) {
        if (ch < 15) { CP_WAIT(1); } else { CP_WAIT(0); }
        __syncthreads();
        if (ch + 2 <= 15) issue((ch + 2) % 3, (ch + 2) * 64);

        uint32_t sA = sb + (ch % 3) * STAGE_E * 2;
        uint32_t sB = sA + AELE * 2;
#pragma unroll
        for (int ks = 0; ks < 4; ks++) {
            uint32_t ah[2][4];
#pragma unroll
            for (int mt = 0; mt < 2; mt++)
                ldm_x4(ah[mt], sA + ((wm + mt * 16) * 72 + ks * 16) * 2 + lnA);
            uint32_t bfh[2][4];
#pragma unroll
            for (int bg = 0; bg < 2; bg++)
                ldm_x4_t(bfh[bg], sB + (ks * 16 * 136 + wn + bg * 16) * 2 + lnB);
#pragma unroll
            for (int mt = 0; mt < 2; mt++)
#pragma unroll
                for (int nt = 0; nt < 4; nt++)
                    mma16816(c[mt][nt], ah[mt], &bfh[nt >> 1][(nt & 1) * 2]);
        }
    }

#pragma unroll
    for (int mt = 0; mt < 2; mt++)
#pragma unroll
        for (int nt = 0; nt < 4; nt++) {
            const int dcol = wn + nt * 8 + q * 2;
            const int col = n0 + dcol;
#pragma unroll
            for (int hh = 0; hh < 2; hh++) {
                const int m = m0 + wm + mt * 16 + g + hh * 8;
                float v0 = c[mt][nt][hh * 2 + 0];
                float v1 = c[mt][nt][hh * 2 + 1];
                if (MODE == 0) {
                    const int bi = m >> 9, ns = m & 511, h = n0 >> 7;
                    v0 = (v0 + bias[col])     * g_gate2[bi * FEAT + col];
                    v1 = (v1 + bias[col + 1]) * g_gate2[bi * FEAT + col + 1];
                    size_t o = (((size_t)bi * NH + h) * NUMS + ns) * HLEN + dcol;
                    *(uint32_t*)&g_Qh[o] = pack2(v0, v1);
                } else {
                    float2 o;
                    o.x = fmaxf(v0 + bias[col], 0.f)     + res[(size_t)m * FEAT + col];
                    o.y = fmaxf(v1 + bias[col + 1], 0.f) + res[(size_t)m * FEAT + col + 1];
                    *(float2*)&Cout[(size_t)m * FEAT + col] = o;
                }
            }
        }
}

// ================================================================
// attention, register-resident S/softmax, per (b, h, 64 Q-rows).
// smem: Q[64][136] bf16 @0 (17408); P[64][520] bf16 @17408 (66560);
//       KV 3 slots @83968 (3x17408); redbuf 2x64x4 f32 @136192 (2048).
#define QOFF 0
#define POFF 17408
#define KVOFF 83968
#define REDOFF 136192
#define ATT_SMEM 138240
__global__ void __launch_bounds__(512) attn_mma(
    const unsigned* __restrict__ mask, float* __restrict__ att_out)
{
    extern __shared__ char smc[];
    const uint32_t sb = smem_u32(smc);
    float* red = (float*)(smc + REDOFF);
    const int tid = threadIdx.x;
    const int wid = tid >> 5, lane = tid & 31;
    const int g = lane >> 2, q = lane & 3;
    const int n0 = blockIdx.x * 64;
    const int h = blockIdx.y, b = blockIdx.z;

    const uint32_t lnB = ((lane & 15) * 136 + (lane >> 4) * 8) * 2;
    const uint32_t KVB = sb + KVOFF;
    const uint32_t PB  = sb + POFF;
    const unsigned* mbase = mask + (size_t)b * NUMS * NUMS;

    auto issueKV = [&](int ck, int slot) {
        const int row = tid >> 3, cb = (tid & 7) * 16;
        size_t so = ((size_t)b * NUMS + ck * 64 + row) * FEAT + h * HLEN + cb;
        uint32_t d = KVB + slot * 17408 + (row * 136 + cb) * 2;
        cpa16(d,      g_x1h + so);
        cpa16(d + 16, g_x1h + so + 8);
        CP_COMMIT();
    };

    // ---- prologue: Q into its own region; K chunks 0,1 into slots 0,1
    {
        const int row = tid >> 3, cb = (tid & 7) * 16;
        size_t so = (((size_t)b * NH + h) * NUMS + n0 + row) * HLEN + cb;
        uint32_t d = sb + QOFF + (row * 136 + cb) * 2;
        cpa16(d,      g_Qh + so);
        cpa16(d + 16, g_Qh + so + 8);
        CP_COMMIT();
    }
    issueKV(0, 0);
    issueKV(1, 1);

    const int wm2 = (wid >> 2) * 16, wn2 = (wid & 3) * 16;
    const int r0 = wm2 + g, r1 = r0 + 8;

    // S fragments: [chunk][nt][4]  (rows r0,r1 ; cols ck*64+wn2+nt*8+q*2)
    float cA[8][2][4];

    // ---- phase 1: S = Q K^T, 8 chunks of 64 keys; mask applied in registers
#pragma unroll
    for (int ck = 0; ck < 8; ck++) {
        if (ck == 0) { CP_WAIT(1); }              // Q + K0 done
        else if (ck < 7) { CP_WAIT(1); }
        else { CP_WAIT(0); }
        __syncthreads();
        if (ck + 2 <= 7) issueKV(ck + 2, (ck + 2) % 3);

        uint32_t kbh = KVB + (ck % 3) * 17408;
        float* c0 = cA[ck][0];
        float* c1 = cA[ck][1];
#pragma unroll
        for (int k = 0; k < 4; k++) { c0[k] = 0.f; c1[k] = 0.f; }
#pragma unroll
        for (int ks = 0; ks < 8; ks++) {
            uint32_t qf[4], kh[4];
            ldm_x4(qf, sb + QOFF + (wm2 * 136 + ks * 16) * 2 + lnB);
            ldm_x4(kh, kbh + (wn2 * 136 + ks * 16) * 2 + lnB);
            uint32_t b0h[2] = {kh[0], kh[2]}, b1h[2] = {kh[1], kh[3]};
            mma16816(c0, qf, b0h);
            mma16816(c1, qf, b1h);
        }
        // fold mask (register-resident)
#pragma unroll
        for (int nt = 0; nt < 2; nt++) {
            const int col = ck * 64 + wn2 + nt * 8 + q * 2;
            uint2 m0v = *(const uint2*)&mbase[(size_t)(n0 + r0) * NUMS + col];
            uint2 m1v = *(const uint2*)&mbase[(size_t)(n0 + r1) * NUMS + col];
            if (m0v.x) cA[ck][nt][0] = -1e9f;
            if (m0v.y) cA[ck][nt][1] = -1e9f;
            if (m1v.x) cA[ck][nt][2] = -1e9f;
            if (m1v.y) cA[ck][nt][3] = -1e9f;
        }
    }

    // ---- phase 2: register softmax (quad shfl + cross-warp smem reduce)
    float mx0 = -1e30f, mx1 = -1e30f;
#pragma unroll
    for (int ck = 0; ck < 8; ck++)
#pragma unroll
        for (int nt = 0; nt < 2; nt++) {
            mx0 = fmaxf(mx0, fmaxf(cA[ck][nt][0], cA[ck][nt][1]));
            mx1 = fmaxf(mx1, fmaxf(cA[ck][nt][2], cA[ck][nt][3]));
        }
    mx0 = fmaxf(mx0, __shfl_xor_sync(0xffffffffu, mx0, 1));
    mx0 = fmaxf(mx0, __shfl_xor_sync(0xffffffffu, mx0, 2));
    mx1 = fmaxf(mx1, __shfl_xor_sync(0xffffffffu, mx1, 1));
    mx1 = fmaxf(mx1, __shfl_xor_sync(0xffffffffu, mx1, 2));
    if (q == 0) {
        red[r0 * 4 + (wid & 3)] = mx0;
        red[r1 * 4 + (wid & 3)] = mx1;
    }
    __syncthreads();                 // also: all K-slot reads complete
    issueKV(0, 0);                   // prefetch V chunks over the softmax
    issueKV(1, 1);
    mx0 = fmaxf(fmaxf(red[r0 * 4 + 0], red[r0 * 4 + 1]),
                fmaxf(red[r0 * 4 + 2], red[r0 * 4 + 3]));
    mx1 = fmaxf(fmaxf(red[r1 * 4 + 0], red[r1 * 4 + 1]),
                fmaxf(red[r1 * 4 + 2], red[r1 * 4 + 3]));

    float s0 = 0.f, s1 = 0.f;
#pragma unroll
    for (int ck = 0; ck < 8; ck++)
#pragma unroll
        for (int nt = 0; nt < 2; nt++) {
            float e0 = __expf(cA[ck][nt][0] - mx0);
            float e1 = __expf(cA[ck][nt][1] - mx0);
            float e2 = __expf(cA[ck][nt][2] - mx1);
            float e3 = __expf(cA[ck][nt][3] - mx1);
            cA[ck][nt][0] = e0; cA[ck][nt][1] = e1;
            cA[ck][nt][2] = e2; cA[ck][nt][3] = e3;
            s0 += e0 + e1; s1 += e2 + e3;
        }
    s0 += __shfl_xor_sync(0xffffffffu, s0, 1);
    s0 += __shfl_xor_sync(0xffffffffu, s0, 2);
    s1 += __shfl_xor_sync(0xffffffffu, s1, 1);
    s1 += __shfl_xor_sync(0xffffffffu, s1, 2);
    if (q == 0) {
        red[256 + r0 * 4 + (wid & 3)] = s0;
        red[256 + r1 * 4 + (wid & 3)] = s1;
    }
    __syncthreads();
    float inv0 = 1.0f / (red[256 + r0 * 4 + 0] + red[256 + r0 * 4 + 1] +
                         red[256 + r0 * 4 + 2] + red[256 + r0 * 4 + 3]);
    float inv1 = 1.0f / (red[256 + r1 * 4 + 0] + red[256 + r1 * 4 + 1] +
                         red[256 + r1 * 4 + 2] + red[256 + r1 * 4 + 3]);

    // write att (fp32, global) + P (bf16, smem)
    float* arow0 = att_out + (((size_t)b * NH + h) * NUMS + (n0 + r0)) * NUMS;
    float* arow1 = att_out + (((size_t)b * NH + h) * NUMS + (n0 + r1)) * NUMS;
#pragma unroll
    for (int ck = 0; ck < 8; ck++)
#pragma unroll
        for (int nt = 0; nt < 2; nt++) {
            const int col = ck * 64 + wn2 + nt * 8 + q * 2;
            float p0 = cA[ck][nt][0] * inv0, p1 = cA[ck][nt][1] * inv0;
            float p2 = cA[ck][nt][2] * inv1, p3 = cA[ck][nt][3] * inv1;
            *(float2*)&arow0[col] = make_float2(p0, p1);
            *(float2*)&arow1[col] = make_float2(p2, p3);
            *(uint32_t*)(smc + POFF + (r0 * 520 + col) * 2) = pack2(p0, p1);
            *(uint32_t*)(smc + POFF + (r1 * 520 + col) * 2) = pack2(p2, p3);
        }
    __syncthreads();                 // P complete

    // ---- phase 3: O = att @ V, 8 chunks of 64 keys (V via 3-slot cp.async)
    const int wm3 = (wid >> 2) * 16, wn3 = (wid & 3) * 32;
    const uint32_t lnP = ((lane & 15) * 520 + (lane >> 4) * 8) * 2;
    float c3[4][4];
#pragma unroll
    for (int i = 0; i < 4; i++)
#pragma unroll
        for (int k = 0; k < 4; k++) c3[i][k] = 0.f;

    for (int kt = 0; kt < 8; kt++) {
        if (kt < 7) { CP_WAIT(1); } else { CP_WAIT(0); }
        __syncthreads();
        if (kt + 2 <= 7) issueKV(kt + 2, (kt + 2) % 3);

        uint32_t vbh = KVB + (kt % 3) * 17408;
#pragma unroll
        for (int ks = 0; ks < 4; ks++) {
            uint32_t ph[4];
            ldm_x4(ph, PB + (wm3 * 520 + kt * 64 + ks * 16) * 2 + lnP);
#pragma unroll
            for (int vg = 0; vg < 2; vg++) {
                uint32_t vh[4];
                ldm_x4_t(vh, vbh + (ks * 16 * 136 + wn3 + vg * 16) * 2 + lnB);
                mma16816(c3[vg * 2 + 0], ph, &vh[0]);
                mma16816(c3[vg * 2 + 1], ph, &vh[2]);
            }
        }
    }

    // ---- epilogue: O -> g_Oh [b, n, f] (bf16)
#pragma unroll
    for (int vg = 0; vg < 2; vg++)
#pragma unroll
        for (int hf = 0; hf < 2; hf++) {
            const float* cc = c3[vg * 2 + hf];
            const int d = wn3 + vg * 16 + hf * 8 + q * 2;
            const int row = wm3 + g;
            size_t o0 = ((size_t)b * NUMS + n0 + row) * FEAT + h * HLEN + d;
            size_t o1 = o0 + 8 * FEAT;
            *(uint32_t*)&g_Oh[o0] = pack2(cc[0], cc[1]);
            *(uint32_t*)&g_Oh[o1] = pack2(cc[2], cc[3]);
        }
}

// ----------------------------------------------------------------
extern "C" void kernel_launch(void* const* d_in, const int* in_sizes, int n_in,
                              void* d_out, int out_size) {
    const float*    x1   = (const float*)d_in[0];
    const float*    x2   = (const float*)d_in[1];
    const unsigned* mask = (const unsigned*)d_in[4];
    const float*    Wq   = (const float*)d_in[5];
    const float*    bq   = (const float*)d_in[6];
    const float*    Wl   = (const float*)d_in[7];
    const float*    bl   = (const float*)d_in[8];
    float* out = (float*)d_out;
    float* att = out + (size_t)BSZ * NUMS * FEAT;   // tuple: (xout, att)

    dim3 gg(FEAT / 256, BSZ);
    gate_kernel<<<gg, 256>>>(x2);

    { void* p; cudaGetSymbolAddress(&p, g_x1h);
      cvt_h<<<(int)(NF / 4 / 256), 256>>>(x1, (__nv_bfloat16*)p, (int)(NF / 4)); }
    { void* p; cudaGetSymbolAddress(&p, g_Wqh);
      cvt_h<<<FEAT * FEAT / 4 / 256, 256>>>(Wq, (__nv_bfloat16*)p, FEAT * FEAT / 4); }
    { void* p; cudaGetSymbolAddress(&p, g_Wlh);
      cvt_h<<<FEAT * FEAT / 4 / 256, 256>>>(Wl, (__nv_bfloat16*)p, FEAT * FEAT / 4); }

    cudaFuncSetAttribute(gemm_mma<0>, cudaFuncAttributeMaxDynamicSharedMemorySize, GEMM_SMEM);
    cudaFuncSetAttribute(gemm_mma<1>, cudaFuncAttributeMaxDynamicSharedMemorySize, GEMM_SMEM);
    cudaFuncSetAttribute(attn_mma,    cudaFuncAttributeMaxDynamicSharedMemorySize, ATT_SMEM);

    dim3 ggemm(FEAT / 128, (BSZ * NUMS) / 128);
    gemm_mma<0><<<ggemm, 512, GEMM_SMEM>>>(bq, nullptr, nullptr);

    dim3 ga(NUMS / 64, NH, BSZ);
    attn_mma<<<ga, 512, ATT_SMEM>>>(mask, att);

    gemm_mma<1><<<ggemm, 512, GEMM_SMEM>>>(bl, x1, out);
}

// round 12
// speedup vs baseline: 6.3947x; 1.0188x over previous
#include <cuda_runtime.h>
#include <cuda_bf16.h>
#include <cstdint>

#define BSZ  32
#define NUMS 512
#define FEAT 1024
#define NH   8
#define HLEN 128

#define NF ((size_t)BSZ * NUMS * FEAT)
// bf16 scratch (allocation-free rule: __device__ globals)
__device__ __nv_bfloat16 g_x1h[NF];                 // x1 bf16, [b,n,f]
__device__ __nv_bfloat16 g_Qh [NF];                 // Q*(gate^2*scale) bf16, [b,h,n,d]
__device__ __nv_bfloat16 g_Oh [NF];                 // att@V bf16, [b,n,f]
__device__ __nv_bfloat16 g_Wqh[FEAT * FEAT];        // [h,f,d] flat
__device__ __nv_bfloat16 g_Wlh[FEAT * FEAT];        // [f,n]
__device__ float g_gate2[BSZ * FEAT];
__device__ uint32_t g_mbits[BSZ * NUMS * (NUMS / 32)];   // packed mask bits

// ---------------------------------------------------------------- helpers
__device__ __forceinline__ uint32_t smem_u32(const void* p) {
    uint32_t a;
    asm("{ .reg .u64 t; cvta.to.shared.u64 t, %1; cvt.u32.u64 %0, t; }" : "=r"(a) : "l"(p));
    return a;
}
__device__ __forceinline__ uint32_t pack2(float a, float b) {
    __nv_bfloat162 t = __floats2bfloat162_rn(a, b);
    return *(uint32_t*)&t;
}
__device__ __forceinline__ void mma16816(float* c, const uint32_t* a, const uint32_t* b) {
    asm volatile(
        "mma.sync.aligned.m16n8k16.row.col.f32.bf16.bf16.f32 "
        "{%0,%1,%2,%3}, {%4,%5,%6,%7}, {%8,%9}, {%0,%1,%2,%3};"
        : "+f"(c[0]), "+f"(c[1]), "+f"(c[2]), "+f"(c[3])
        : "r"(a[0]), "r"(a[1]), "r"(a[2]), "r"(a[3]), "r"(b[0]), "r"(b[1]));
}
__device__ __forceinline__ void ldm_x4(uint32_t* r, uint32_t sa) {
    asm volatile("ldmatrix.sync.aligned.m8n8.x4.shared.b16 {%0,%1,%2,%3}, [%4];"
        : "=r"(r[0]), "=r"(r[1]), "=r"(r[2]), "=r"(r[3]) : "r"(sa));
}
__device__ __forceinline__ void ldm_x4_t(uint32_t* r, uint32_t sa) {
    asm volatile("ldmatrix.sync.aligned.m8n8.x4.trans.shared.b16 {%0,%1,%2,%3}, [%4];"
        : "=r"(r[0]), "=r"(r[1]), "=r"(r[2]), "=r"(r[3]) : "r"(sa));
}
__device__ __forceinline__ void cpa16(uint32_t dst, const void* src) {
    asm volatile("cp.async.cg.shared.global [%0], [%1], 16;" :: "r"(dst), "l"(src));
}
#define CP_COMMIT() asm volatile("cp.async.commit_group;" ::: "memory")
#define CP_WAIT(n)  asm volatile("cp.async.wait_group %0;" :: "n"(n) : "memory")

// ---------------------------------------------------------------- convert to bf16
__global__ void cvt_h(const float* __restrict__ src, __nv_bfloat16* __restrict__ h, int n4) {
    int i = blockIdx.x * 256 + threadIdx.x;
    if (i < n4) {
        float4 v = ((const float4*)src)[i];
        ((uint2*)h)[i] = make_uint2(pack2(v.x, v.y), pack2(v.z, v.w));
    }
}

// ---------------------------------------------------------------- pack mask -> bits
__global__ void mask_pack(const unsigned* __restrict__ mask) {
    int t = blockIdx.x * 256 + threadIdx.x;          // one thread per element
    unsigned v = mask[t];
    uint32_t w = __ballot_sync(0xffffffffu, v != 0);
    if ((t & 31) == 0) g_mbits[t >> 5] = w;
}

// ---------------------------------------------------------------- gate^2
__global__ void gate_kernel(const float* __restrict__ x2) {
    int b = blockIdx.y;
    int f = blockIdx.x * 256 + threadIdx.x;
    const float* p = x2 + (size_t)b * NUMS * FEAT + f;
    float s = 0.f;
#pragma unroll 8
    for (int n = 0; n < NUMS; n++) s += p[(size_t)n * FEAT];
    float g = s * (1.0f / NUMS);
    g_gate2[b * FEAT + f] = g * g * 0.08838834764831845f;  // 1/sqrt(128)
}

// ================================================================
// pipelined bf16 GEMM (unchanged from R11-passing): k-chunk 64, 3 stages.
#define AELE 9216
#define BELE 8704
#define STAGE_E (AELE + BELE)
#define GEMM_SMEM (3 * STAGE_E * 2)         // 107520 B

template <int MODE>
__global__ void __launch_bounds__(512) gemm_mma(
    const float* __restrict__ bias, const float* __restrict__ res,
    float* __restrict__ Cout)
{
    extern __shared__ __nv_bfloat16 smb[];
    const uint32_t sb = smem_u32(smb);
    const int tid = threadIdx.x;
    const int n0 = blockIdx.x * 128;
    const int m0 = blockIdx.y * 128;
    const int wid = tid >> 5, lane = tid & 31;
    const int wm = (wid >> 2) * 32, wn = (wid & 3) * 32;
    const int g = lane >> 2, q = lane & 3;

    const __nv_bfloat16* Ahg = MODE ? g_Oh : g_x1h;
    const __nv_bfloat16* Bhg = MODE ? g_Wlh + n0 : g_Wqh + (size_t)(n0 >> 7) * FEAT * HLEN;
    const int ldbn = MODE ? FEAT : HLEN;

    const int ar = tid >> 2, ac = (tid & 3) * 16;
    const int br = tid >> 3, bc = (tid & 7) * 16;
    const size_t aoff = (size_t)(m0 + ar) * FEAT + ac;

    auto issue = [&](int slot, int k0) {
        uint32_t s = sb + slot * STAGE_E * 2;
        const __nv_bfloat16* ap = Ahg + aoff + k0;
        uint32_t da = s + (ar * 72 + ac) * 2;
        cpa16(da,      ap);
        cpa16(da + 16, ap + 8);
        const __nv_bfloat16* bp = Bhg + (size_t)(k0 + br) * ldbn + bc;
        uint32_t db = s + AELE * 2 + (br * 136 + bc) * 2;
        cpa16(db,      bp);
        cpa16(db + 16, bp + 8);
        CP_COMMIT();
    };

    float c[2][4][4];
#pragma unroll
    for (int i = 0; i < 2; i++)
#pragma unroll
        for (int j = 0; j < 4; j++)
#pragma unroll
            for (int k = 0; k < 4; k++) c[i][j][k] = 0.f;

    const uint32_t lnA = ((lane & 15) * 72 + (lane >> 4) * 8) * 2;
    const uint32_t lnB = ((lane & 15) * 136 + (lane >> 4) * 8) * 2;

    issue(0, 0);
    issue(1, 64);

    for (int ch = 0; ch < 16; ch++) {
        if (ch < 15) { CP_WAIT(1); } else { CP_WAIT(0); }
        __syncthreads();
        if (ch + 2 <= 15) issue((ch + 2) % 3, (ch + 2) * 64);

        uint32_t sA = sb + (ch % 3) * STAGE_E * 2;
        uint32_t sB = sA + AELE * 2;
#pragma unroll
        for (int ks = 0; ks < 4; ks++) {
            uint32_t ah[2][4];
#pragma unroll
            for (int mt = 0; mt < 2; mt++)
                ldm_x4(ah[mt], sA + ((wm + mt * 16) * 72 + ks * 16) * 2 + lnA);
            uint32_t bfh[2][4];
#pragma unroll
            for (int bg = 0; bg < 2; bg++)
                ldm_x4_t(bfh[bg], sB + (ks * 16 * 136 + wn + bg * 16) * 2 + lnB);
#pragma unroll
            for (int mt = 0; mt < 2; mt++)
#pragma unroll
                for (int nt = 0; nt < 4; nt++)
                    mma16816(c[mt][nt], ah[mt], &bfh[nt >> 1][(nt & 1) * 2]);
        }
    }

#pragma unroll
    for (int mt = 0; mt < 2; mt++)
#pragma unroll
        for (int nt = 0; nt < 4; nt++) {
            const int dcol = wn + nt * 8 + q * 2;
            const int col = n0 + dcol;
#pragma unroll
            for (int hh = 0; hh < 2; hh++) {
                const int m = m0 + wm + mt * 16 + g + hh * 8;
                float v0 = c[mt][nt][hh * 2 + 0];
                float v1 = c[mt][nt][hh * 2 + 1];
                if (MODE == 0) {
                    const int bi = m >> 9, ns = m & 511, h = n0 >> 7;
                    v0 = (v0 + bias[col])     * g_gate2[bi * FEAT + col];
                    v1 = (v1 + bias[col + 1]) * g_gate2[bi * FEAT + col + 1];
                    size_t o = (((size_t)bi * NH + h) * NUMS + ns) * HLEN + dcol;
                    *(uint32_t*)&g_Qh[o] = pack2(v0, v1);
                } else {
                    float2 o;
                    o.x = fmaxf(v0 + bias[col], 0.f)     + res[(size_t)m * FEAT + col];
                    o.y = fmaxf(v1 + bias[col + 1], 0.f) + res[(size_t)m * FEAT + col + 1];
                    *(float2*)&Cout[(size_t)m * FEAT + col] = o;
                }
            }
        }
}

// ================================================================
// attention, register-resident S/softmax, ALL 8 K-chunks resident in smem
// (phase 3 reuses them as V: no loads, no syncs). Bitmask for mask.
// smem: Q[64][136] bf16 @0 (17408); P[64][520] bf16 @17408 (66560);
//       KV 8 slots @83968 (8x17408=139264); redbuf @223232 (2048). total 225280.
#define QOFF 0
#define POFF 17408
#define KVOFF 83968
#define REDOFF 223232
#define ATT_SMEM 225280
__global__ void __launch_bounds__(512) attn_mma(float* __restrict__ att_out)
{
    extern __shared__ char smc[];
    const uint32_t sb = smem_u32(smc);
    float* red = (float*)(smc + REDOFF);
    const int tid = threadIdx.x;
    const int wid = tid >> 5, lane = tid & 31;
    const int g = lane >> 2, q = lane & 3;
    const int n0 = blockIdx.x * 64;
    const int h = blockIdx.y, b = blockIdx.z;

    const uint32_t lnB = ((lane & 15) * 136 + (lane >> 4) * 8) * 2;
    const uint32_t KVB = sb + KVOFF;
    const uint32_t PB  = sb + POFF;

    auto issueKV = [&](int ck) {
        const int row = tid >> 3, cb = (tid & 7) * 16;
        size_t so = ((size_t)b * NUMS + ck * 64 + row) * FEAT + h * HLEN + cb;
        uint32_t d = KVB + ck * 17408 + (row * 136 + cb) * 2;
        cpa16(d,      g_x1h + so);
        cpa16(d + 16, g_x1h + so + 8);
        CP_COMMIT();
    };

    // ---- prologue: Q, then K chunks 0,1 (pipeline depth 2)
    {
        const int row = tid >> 3, cb = (tid & 7) * 16;
        size_t so = (((size_t)b * NH + h) * NUMS + n0 + row) * HLEN + cb;
        uint32_t d = sb + QOFF + (row * 136 + cb) * 2;
        cpa16(d,      g_Qh + so);
        cpa16(d + 16, g_Qh + so + 8);
        CP_COMMIT();
    }
    issueKV(0);
    issueKV(1);

    const int wm2 = (wid >> 2) * 16, wn2 = (wid & 3) * 16;
    const int r0 = wm2 + g, r1 = r0 + 8;
    const uint32_t* mb0 = g_mbits + ((size_t)b * NUMS + n0 + r0) * (NUMS / 32);
    const uint32_t* mb1 = g_mbits + ((size_t)b * NUMS + n0 + r1) * (NUMS / 32);

    // S fragments: [chunk][nt][4]
    float cA[8][2][4];

    // ---- phase 1: S = Q K^T, 8 chunks of 64 keys into distinct slots
#pragma unroll
    for (int ck = 0; ck < 8; ck++) {
        CP_WAIT(1);
        __syncthreads();
        if (ck + 2 <= 7) issueKV(ck + 2);

        uint32_t kbh = KVB + ck * 17408;
        float* c0 = cA[ck][0];
        float* c1 = cA[ck][1];
#pragma unroll
        for (int k = 0; k < 4; k++) { c0[k] = 0.f; c1[k] = 0.f; }
#pragma unroll
        for (int ks = 0; ks < 8; ks++) {
            uint32_t qf[4], kh[4];
            ldm_x4(qf, sb + QOFF + (wm2 * 136 + ks * 16) * 2 + lnB);
            ldm_x4(kh, kbh + (wn2 * 136 + ks * 16) * 2 + lnB);
            uint32_t b0h[2] = {kh[0], kh[2]}, b1h[2] = {kh[1], kh[3]};
            mma16816(c0, qf, b0h);
            mma16816(c1, qf, b1h);
        }
        // fold mask from packed bits (register-resident)
#pragma unroll
        for (int nt = 0; nt < 2; nt++) {
            const int col = ck * 64 + wn2 + nt * 8 + q * 2;
            uint32_t w0 = (mb0[col >> 5] >> (col & 31)) & 3u;
            uint32_t w1 = (mb1[col >> 5] >> (col & 31)) & 3u;
            if (w0 & 1u) cA[ck][nt][0] = -1e9f;
            if (w0 & 2u) cA[ck][nt][1] = -1e9f;
            if (w1 & 1u) cA[ck][nt][2] = -1e9f;
            if (w1 & 2u) cA[ck][nt][3] = -1e9f;
        }
    }

    // ---- phase 2: register softmax (quad shfl + cross-warp smem reduce)
    float mx0 = -1e30f, mx1 = -1e30f;
#pragma unroll
    for (int ck = 0; ck < 8; ck++)
#pragma unroll
        for (int nt = 0; nt < 2; nt++) {
            mx0 = fmaxf(mx0, fmaxf(cA[ck][nt][0], cA[ck][nt][1]));
            mx1 = fmaxf(mx1, fmaxf(cA[ck][nt][2], cA[ck][nt][3]));
        }
    mx0 = fmaxf(mx0, __shfl_xor_sync(0xffffffffu, mx0, 1));
    mx0 = fmaxf(mx0, __shfl_xor_sync(0xffffffffu, mx0, 2));
    mx1 = fmaxf(mx1, __shfl_xor_sync(0xffffffffu, mx1, 1));
    mx1 = fmaxf(mx1, __shfl_xor_sync(0xffffffffu, mx1, 2));
    if (q == 0) {
        red[r0 * 4 + (wid & 3)] = mx0;
        red[r1 * 4 + (wid & 3)] = mx1;
    }
    __syncthreads();
    mx0 = fmaxf(fmaxf(red[r0 * 4 + 0], red[r0 * 4 + 1]),
                fmaxf(red[r0 * 4 + 2], red[r0 * 4 + 3]));
    mx1 = fmaxf(fmaxf(red[r1 * 4 + 0], red[r1 * 4 + 1]),
                fmaxf(red[r1 * 4 + 2], red[r1 * 4 + 3]));

    float s0 = 0.f, s1 = 0.f;
#pragma unroll
    for (int ck = 0; ck < 8; ck++)
#pragma unroll
        for (int nt = 0; nt < 2; nt++) {
            float e0 = __expf(cA[ck][nt][0] - mx0);
            float e1 = __expf(cA[ck][nt][1] - mx0);
            float e2 = __expf(cA[ck][nt][2] - mx1);
            float e3 = __expf(cA[ck][nt][3] - mx1);
            cA[ck][nt][0] = e0; cA[ck][nt][1] = e1;
            cA[ck][nt][2] = e2; cA[ck][nt][3] = e3;
            s0 += e0 + e1; s1 += e2 + e3;
        }
    s0 += __shfl_xor_sync(0xffffffffu, s0, 1);
    s0 += __shfl_xor_sync(0xffffffffu, s0, 2);
    s1 += __shfl_xor_sync(0xffffffffu, s1, 1);
    s1 += __shfl_xor_sync(0xffffffffu, s1, 2);
    if (q == 0) {
        red[256 + r0 * 4 + (wid & 3)] = s0;
        red[256 + r1 * 4 + (wid & 3)] = s1;
    }
    __syncthreads();
    float inv0 = 1.0f / (red[256 + r0 * 4 + 0] + red[256 + r0 * 4 + 1] +
                         red[256 + r0 * 4 + 2] + red[256 + r0 * 4 + 3]);
    float inv1 = 1.0f / (red[256 + r1 * 4 + 0] + red[256 + r1 * 4 + 1] +
                         red[256 + r1 * 4 + 2] + red[256 + r1 * 4 + 3]);

    // write att (fp32, streaming) + P (bf16, smem)
    float* arow0 = att_out + (((size_t)b * NH + h) * NUMS + (n0 + r0)) * NUMS;
    float* arow1 = att_out + (((size_t)b * NH + h) * NUMS + (n0 + r1)) * NUMS;
#pragma unroll
    for (int ck = 0; ck < 8; ck++)
#pragma unroll
        for (int nt = 0; nt < 2; nt++) {
            const int col = ck * 64 + wn2 + nt * 8 + q * 2;
            float p0 = cA[ck][nt][0] * inv0, p1 = cA[ck][nt][1] * inv0;
            float p2 = cA[ck][nt][2] * inv1, p3 = cA[ck][nt][3] * inv1;
            __stcs((float2*)&arow0[col], make_float2(p0, p1));
            __stcs((float2*)&arow1[col], make_float2(p2, p3));
            *(uint32_t*)(smc + POFF + (r0 * 520 + col) * 2) = pack2(p0, p1);
            *(uint32_t*)(smc + POFF + (r1 * 520 + col) * 2) = pack2(p2, p3);
        }
    __syncthreads();                 // P complete

    // ---- phase 3: O = att @ V — V chunks already resident; pure compute
    const int wm3 = (wid >> 2) * 16, wn3 = (wid & 3) * 32;
    const uint32_t lnP = ((lane & 15) * 520 + (lane >> 4) * 8) * 2;
    float c3[4][4];
#pragma unroll
    for (int i = 0; i < 4; i++)
#pragma unroll
        for (int k = 0; k < 4; k++) c3[i][k] = 0.f;

    for (int kt = 0; kt < 8; kt++) {
        uint32_t vbh = KVB + kt * 17408;
#pragma unroll
        for (int ks = 0; ks < 4; ks++) {
            uint32_t ph[4];
            ldm_x4(ph, PB + (wm3 * 520 + kt * 64 + ks * 16) * 2 + lnP);
#pragma unroll
            for (int vg = 0; vg < 2; vg++) {
                uint32_t vh[4];
                ldm_x4_t(vh, vbh + (ks * 16 * 136 + wn3 + vg * 16) * 2 + lnB);
                mma16816(c3[vg * 2 + 0], ph, &vh[0]);
                mma16816(c3[vg * 2 + 1], ph, &vh[2]);
            }
        }
    }

    // ---- epilogue: O -> g_Oh [b, n, f] (bf16)
#pragma unroll
    for (int vg = 0; vg < 2; vg++)
#pragma unroll
        for (int hf = 0; hf < 2; hf++) {
            const float* cc = c3[vg * 2 + hf];
            const int d = wn3 + vg * 16 + hf * 8 + q * 2;
            const int row = wm3 + g;
            size_t o0 = ((size_t)b * NUMS + n0 + row) * FEAT + h * HLEN + d;
            size_t o1 = o0 + 8 * FEAT;
            *(uint32_t*)&g_Oh[o0] = pack2(cc[0], cc[1]);
            *(uint32_t*)&g_Oh[o1] = pack2(cc[2], cc[3]);
        }
}

// ----------------------------------------------------------------
extern "C" void kernel_launch(void* const* d_in, const int* in_sizes, int n_in,
                              void* d_out, int out_size) {
    const float*    x1   = (const float*)d_in[0];
    const float*    x2   = (const float*)d_in[1];
    const unsigned* mask = (const unsigned*)d_in[4];
    const float*    Wq   = (const float*)d_in[5];
    const float*    bq   = (const float*)d_in[6];
    const float*    Wl   = (const float*)d_in[7];
    const float*    bl   = (const float*)d_in[8];
    float* out = (float*)d_out;
    float* att = out + (size_t)BSZ * NUMS * FEAT;   // tuple: (xout, att)

    dim3 gg(FEAT / 256, BSZ);
    gate_kernel<<<gg, 256>>>(x2);

    { void* p; cudaGetSymbolAddress(&p, g_x1h);
      cvt_h<<<(int)(NF / 4 / 256), 256>>>(x1, (__nv_bfloat16*)p, (int)(NF / 4)); }
    { void* p; cudaGetSymbolAddress(&p, g_Wqh);
      cvt_h<<<FEAT * FEAT / 4 / 256, 256>>>(Wq, (__nv_bfloat16*)p, FEAT * FEAT / 4); }
    { void* p; cudaGetSymbolAddress(&p, g_Wlh);
      cvt_h<<<FEAT * FEAT / 4 / 256, 256>>>(Wl, (__nv_bfloat16*)p, FEAT * FEAT / 4); }

    mask_pack<<<BSZ * NUMS * NUMS / 256, 256>>>(mask);

    cudaFuncSetAttribute(gemm_mma<0>, cudaFuncAttributeMaxDynamicSharedMemorySize, GEMM_SMEM);
    cudaFuncSetAttribute(gemm_mma<1>, cudaFuncAttributeMaxDynamicSharedMemorySize, GEMM_SMEM);
    cudaFuncSetAttribute(attn_mma,    cudaFuncAttributeMaxDynamicSharedMemorySize, ATT_SMEM);

    dim3 ggemm(FEAT / 128, (BSZ * NUMS) / 128);
    gemm_mma<0><<<ggemm, 512, GEMM_SMEM>>>(bq, nullptr, nullptr);

    dim3 ga(NUMS / 64, NH, BSZ);
    attn_mma<<<ga, 512, ATT_SMEM>>>(att);

    gemm_mma<1><<<ggemm, 512, GEMM_SMEM>>>(bl, x1, out);
}